// round 12
// baseline (speedup 1.0000x reference)
#include <cuda_runtime.h>
#include <cuda_bf16.h>
#include <cstdint>

// ---------------------------------------------------------------------------
// Conv_DCFD on sm_100 (no tcgen05 in this toolchain): conv1, conv2 and the
// final 1x1 GEMM all run on the tensor pipe via mma.sync tf32 (rna-rounded).
// R12: k-permuted smem layouts (perm8) -> frag loads become LDS.64,
// halving LDS issues per MMA in conv1/conv2/k3b. Bit-identical numerics.
// Shapes: N=16,H=64,W=64,C=128, inter=64, bases=36, M=6, O=256
// ---------------------------------------------------------------------------

#define NB   16
#define HH   64
#define WW   64
#define CIN  128
#define CMID 64
#define BSZ  36
#define OO   256

// scratch (no cudaMalloc allowed)
__device__ float g_h   [NB * HH * WW * CMID];     // 16.8 MB
__device__ float g_dyn [NB * HH * WW * 54];       // 14.2 MB
__device__ float g_A   [NB * HH * WW * 768];      // 201 MB (tf32, k-permuted)
__device__ float g_Bt  [OO * 768];                // 768 KB (B^T, tf32, k-permuted)
__device__ float g_W1t [9 * CMID * CIN];          // w1^T per tap (ci-permuted)
__device__ float g_W2t [48 * 576];                // w2^T co-major (k-permuted)

__device__ __forceinline__ void cp_async16(void* smem_dst, const void* gmem_src) {
    unsigned s = (unsigned)__cvta_generic_to_shared(smem_dst);
    asm volatile("cp.async.cg.shared.global [%0], [%1], 16;\n" :: "r"(s), "l"(gmem_src));
}
__device__ __forceinline__ void cp_commit() { asm volatile("cp.async.commit_group;\n"); }
template<int N> __device__ __forceinline__ void cp_wait() {
    asm volatile("cp.async.wait_group %0;\n" :: "n"(N));
}
__device__ __forceinline__ uint32_t tf32_rna(float v) {
    uint32_t r;
    asm("cvt.rna.tf32.f32 %0, %1;" : "=r"(r) : "f"(v));
    return r;
}
// permute within each 8-float k-group: orig k -> (k&~7) | ((k&3)<<1) | ((k>>2)&1)
// so that (t4, t4+4) land at adjacent positions (2*t4, 2*t4+1).
__device__ __host__ __forceinline__ int perm8(int k) {
    return (k & ~7) | ((k & 3) << 1) | ((k >> 2) & 1);
}
__device__ __forceinline__ void mma_tf32(float* d, const uint32_t* a, const uint32_t* b) {
    asm volatile(
        "mma.sync.aligned.m16n8k8.row.col.f32.tf32.tf32.f32 "
        "{%0,%1,%2,%3}, {%4,%5,%6,%7}, {%8,%9}, {%0,%1,%2,%3};"
        : "+f"(d[0]), "+f"(d[1]), "+f"(d[2]), "+f"(d[3])
        : "r"(a[0]), "r"(a[1]), "r"(a[2]), "r"(a[3]), "r"(b[0]), "r"(b[1]));
}

// ===========================================================================
// prep kernels: transpose + tf32-round + k-permute weights
// ===========================================================================
__global__ void prepW_kernel(const float* __restrict__ w1) {
    const int bx = blockIdx.x;          // kk*64+co (576)
    const int t  = threadIdx.x;         // ci (128)
    const int kk = bx >> 6, co = bx & 63;
    g_W1t[bx * 128 + perm8(t)] = __uint_as_float(tf32_rna(w1[(kk * 128 + t) * 64 + co]));
}

__global__ void prepW2_kernel(const float* __restrict__ w2) {
    const int n = blockIdx.x;           // 0..47 (co, padded)
    const int k = threadIdx.x;          // 0..575 (kk*64+ci)
    float v = 0.f;
    if (n < BSZ) {
        const int kk = k >> 6, ci = k & 63;
        v = w2[(kk * 64 + ci) * BSZ + n];
    }
    g_W2t[n * 576 + perm8(k)] = __uint_as_float(tf32_rna(v));
}

__global__ void prepB_kernel(const float* __restrict__ coef) {
    const int n = blockIdx.x;
    const int t = threadIdx.x;
    #pragma unroll
    for (int q = 0; q < 3; q++) {
        int k = q * 256 + t;
        g_Bt[n * 768 + perm8(k)] = __uint_as_float(tf32_rna(coef[k * OO + n]));
    }
}

// ===========================================================================
// Kernel 1: conv1 via mma.sync tf32 + BN(axis=H) + ReLU -> g_h
// grid = 512 (2 rows), block 256 (8 warps, 4m x 2n), warp 32px x 32co.
// k-permuted slab/wbuf -> LDS.64 frag loads. Strides 136 (== 8 mod 32).
// ===========================================================================
#define C1_SSTR  136
#define C1_SLAB  (264 * C1_SSTR)        // 35904 floats
#define C1_WSTR  136
#define C1_WCH   (CMID * C1_WSTR)       // 8704 floats
#define C1_SMEM  ((C1_SLAB + 2 * C1_WCH) * 4)   // 213248 B

__global__ __launch_bounds__(256, 1)
void conv1_kernel(const float* __restrict__ x, const float* __restrict__ b1,
                  const float* __restrict__ gamma1, const float* __restrict__ beta1) {
    extern __shared__ float sm[];
    float* slab = sm;
    float* wbuf = sm + C1_SLAB;

    const int t  = threadIdx.x;
    const int bx = blockIdx.x;
    const int nb = bx >> 5;
    const int h0 = (bx & 31) << 1;

    // preload weight chunk 0 (64 co rows x 32 float4 segs; rows already permuted)
    for (int i = t; i < 2048; i += 256) {
        int row = i >> 5, seg = i & 31;
        cp_async16(wbuf + row * C1_WSTR + seg * 4, g_W1t + row * 128 + seg * 4);
    }
    cp_commit();

    // slab: rows h0-1..h0+2 (4), cols -1..64 (66), 128 ci, tf32 + perm8 over ci
    const float4* x4 = (const float4*)x;
    for (int idx = t; idx < 4 * 66 * 32; idx += 256) {
        int ci4 = idx & 31;
        int col = (idx >> 5) % 66;
        int r   = idx / (32 * 66);
        int hh  = h0 + r - 1, ww = col - 1;
        float4 v = make_float4(0.f, 0.f, 0.f, 0.f);
        if (hh >= 0 && hh < HH && ww >= 0 && ww < WW)
            v = x4[((((nb << 6) + hh) << 6) + ww) * 32 + ci4];
        float* dst = slab + (r * 66 + col) * C1_SSTR + (ci4 >> 1) * 8 + (ci4 & 1);
        dst[0] = __uint_as_float(tf32_rna(v.x));
        dst[2] = __uint_as_float(tf32_rna(v.y));
        dst[4] = __uint_as_float(tf32_rna(v.z));
        dst[6] = __uint_as_float(tf32_rna(v.w));
    }
    cp_wait<0>();
    __syncthreads();

    const int wid  = t >> 5;
    const int lane = t & 31;
    const int g    = lane >> 2;
    const int t4   = lane & 3;
    const int wm   = wid >> 1;           // 0..3  (32-px group)
    const int wn   = wid & 1;            // 0..1  (32-co group)
    const int p0   = wm << 5;
    const int r    = p0 >> 6;
    const int col0 = p0 & 63;

    float d[2][4][4] = {};

    for (int kk = 0; kk < 9; kk++) {
        const float* wb = wbuf + (kk & 1) * C1_WCH;
        if (kk < 8) {
            float* dst = wbuf + ((kk + 1) & 1) * C1_WCH;
            const float* src = g_W1t + (kk + 1) * 8192;
            for (int i = t; i < 2048; i += 256) {
                int row = i >> 5, seg = i & 31;
                cp_async16(dst + row * C1_WSTR + seg * 4, src + row * 128 + seg * 4);
            }
            cp_commit();
        }
        const int kh = kk / 3, kw = kk % 3;
        const float* arow = slab + ((r + kh) * 66 + kw + col0 + g) * C1_SSTR + (t4 << 1);

        #pragma unroll
        for (int kt = 0; kt < 16; kt++) {
            const int k0 = kt << 3;
            uint32_t a[2][4], b[4][2];
            #pragma unroll
            for (int mi = 0; mi < 2; mi++) {
                const float* ap = arow + (mi << 4) * C1_SSTR + k0;
                float2 lo = *(const float2*)ap;
                float2 hi = *(const float2*)(ap + 8 * C1_SSTR);
                a[mi][0] = __float_as_uint(lo.x);
                a[mi][1] = __float_as_uint(hi.x);
                a[mi][2] = __float_as_uint(lo.y);
                a[mi][3] = __float_as_uint(hi.y);
            }
            #pragma unroll
            for (int ni = 0; ni < 4; ni++) {
                float2 bv = *(const float2*)(wb + ((wn << 5) + (ni << 3) + g) * C1_WSTR
                                             + k0 + (t4 << 1));
                b[ni][0] = __float_as_uint(bv.x);
                b[ni][1] = __float_as_uint(bv.y);
            }
            #pragma unroll
            for (int mi = 0; mi < 2; mi++)
                #pragma unroll
                for (int ni = 0; ni < 4; ni++)
                    mma_tf32(d[mi][ni], a[mi], b[ni]);
        }
        cp_wait<0>();
        __syncthreads();
    }

    const float invs = rsqrtf(1.0f + 1e-3f);
    const float gs = gamma1[h0 + r] * invs;
    const float bb = beta1[h0 + r];
    #pragma unroll
    for (int mi = 0; mi < 2; mi++) {
        const int p = p0 + (mi << 4) + g;
        float* r0 = g_h + ((size_t)(bx << 7) + p) * CMID;
        float* r1 = r0 + 8 * CMID;
        #pragma unroll
        for (int ni = 0; ni < 4; ni++) {
            const int c = (wn << 5) + (ni << 3) + (t4 << 1);
            const float bc0 = b1[c], bc1 = b1[c + 1];
            float2 v0, v1;
            v0.x = fmaxf(fmaf(d[mi][ni][0] + bc0, gs, bb), 0.f);
            v0.y = fmaxf(fmaf(d[mi][ni][1] + bc1, gs, bb), 0.f);
            v1.x = fmaxf(fmaf(d[mi][ni][2] + bc0, gs, bb), 0.f);
            v1.y = fmaxf(fmaf(d[mi][ni][3] + bc1, gs, bb), 0.f);
            *(float2*)(r0 + c) = v0;
            *(float2*)(r1 + c) = v1;
        }
    }
}

// ===========================================================================
// Kernel 2: conv2 via mma.sync tf32 + BN + ReLU + xFB -> g_dyn
// grid = 256 (4 rows), block 512 (16 warps, 8m x 2n), warp 32px x 24co.
// k-permuted slab (stride 72) + ws (stride 584) -> LDS.64 frag loads.
// ===========================================================================
#define C2_SSTR  72
#define C2_SLAB  (396 * C2_SSTR)        // 28512 floats
#define C2_WSTR  584
#define C2_WS    (48 * C2_WSTR)         // 28032 floats
#define C2_SMEM  ((C2_SLAB + C2_WS + 64) * 4)   // 226432 B

__global__ __launch_bounds__(512, 1)
void conv2_kernel(const float* __restrict__ b2, const float* __restrict__ gamma2,
                  const float* __restrict__ beta2, const float* __restrict__ bases) {
    extern __shared__ float sm[];
    float* slab = sm;
    float* ws   = sm + C2_SLAB;
    float* bss  = sm + C2_SLAB + C2_WS;

    const int t  = threadIdx.x;
    const int bx = blockIdx.x;
    const int nb = bx >> 4;
    const int h0 = (bx & 15) << 2;

    // w2s: 48 rows x 144 float4 segs (rows already k-permuted in g_W2t)
    for (int i = t; i < 6912; i += 512) {
        int row = i / 144, seg = i % 144;
        cp_async16(ws + row * C2_WSTR + seg * 4, g_W2t + row * 576 + seg * 4);
    }
    cp_commit();
    if (t < 54) bss[t] = bases[t];

    // slab: g_h rows h0-1..h0+4 (6), cols -1..64 (66), 64 ci, perm8 over ci
    const float4* h4 = (const float4*)g_h;
    for (int idx = t; idx < 6 * 66 * 16; idx += 512) {
        int seg = idx & 15;
        int pos = idx >> 4;
        int r   = pos / 66, col = pos % 66;
        int hh  = h0 + r - 1, ww = col - 1;
        float4 v = make_float4(0.f, 0.f, 0.f, 0.f);
        if (hh >= 0 && hh < HH && ww >= 0 && ww < WW)
            v = h4[(size_t)((((nb << 6) + hh) << 6) + ww) * 16 + seg];
        float* dst = slab + (r * 66 + col) * C2_SSTR + (seg >> 1) * 8 + (seg & 1);
        dst[0] = v.x;
        dst[2] = v.y;
        dst[4] = v.z;
        dst[6] = v.w;
    }
    cp_wait<0>();
    __syncthreads();

    const int wid  = t >> 5;
    const int lane = t & 31;
    const int g    = lane >> 2;
    const int t4   = lane & 3;
    const int wm   = wid >> 1;
    const int wn   = wid & 1;
    const int p0   = wm << 5;
    const int r    = p0 >> 6;
    const int wcol = p0 & 63;

    float d[2][3][4] = {};

    #pragma unroll
    for (int kk = 0; kk < 9; kk++) {
        const int kh = kk / 3, kw = kk % 3;
        const float* arow = slab + ((r + kh) * 66 + kw + wcol + g) * C2_SSTR + (t4 << 1);
        const float* brow = ws + (wn * 24 + g) * C2_WSTR + kk * 64 + (t4 << 1);
        #pragma unroll
        for (int kt = 0; kt < 8; kt++) {
            const int k0 = kt << 3;
            uint32_t a[2][4], b[3][2];
            #pragma unroll
            for (int mi = 0; mi < 2; mi++) {
                const float* ap = arow + (mi << 4) * C2_SSTR + k0;
                float2 lo = *(const float2*)ap;
                float2 hi = *(const float2*)(ap + 8 * C2_SSTR);
                a[mi][0] = __float_as_uint(lo.x);
                a[mi][1] = __float_as_uint(hi.x);
                a[mi][2] = __float_as_uint(lo.y);
                a[mi][3] = __float_as_uint(hi.y);
            }
            #pragma unroll
            for (int ni = 0; ni < 3; ni++) {
                float2 bv = *(const float2*)(brow + (ni << 3) * C2_WSTR + k0);
                b[ni][0] = __float_as_uint(bv.x);
                b[ni][1] = __float_as_uint(bv.y);
            }
            #pragma unroll
            for (int mi = 0; mi < 2; mi++)
                #pragma unroll
                for (int ni = 0; ni < 3; ni++)
                    mma_tf32(d[mi][ni], a[mi], b[ni]);
        }
    }
    __syncthreads();

    float* bfs = ws;
    const float invs = rsqrtf(1.0f + 1e-3f);
    const float gs = gamma2[h0 + r] * invs;
    const float bb = beta2[h0 + r];
    #pragma unroll
    for (int mi = 0; mi < 2; mi++) {
        const int p = p0 + (mi << 4) + g;
        #pragma unroll
        for (int ni = 0; ni < 3; ni++) {
            const int c = wn * 24 + (ni << 3) + (t4 << 1);
            if (c < BSZ) {
                const float bj0 = b2[c], bj1 = b2[c + 1];
                bfs[p * 37 + c]           = fmaxf(fmaf(d[mi][ni][0] + bj0, gs, bb), 0.f);
                bfs[p * 37 + c + 1]       = fmaxf(fmaf(d[mi][ni][1] + bj1, gs, bb), 0.f);
                bfs[(p + 8) * 37 + c]     = fmaxf(fmaf(d[mi][ni][2] + bj0, gs, bb), 0.f);
                bfs[(p + 8) * 37 + c + 1] = fmaxf(fmaf(d[mi][ni][3] + bj1, gs, bb), 0.f);
            }
        }
    }
    __syncthreads();

    const int pp = t >> 1;
    const int half = t & 1;
    const float* bf = bfs + pp * 37;
    const int rr = pp >> 6, pw = pp & 63;
    float* outp = g_dyn + (size_t)((((nb << 6) + h0 + rr) << 6) + pw) * 54;
    #pragma unroll
    for (int q = 0; q < 27; q++) {
        int idx = half * 27 + q;
        int m = idx / 9, l = idx % 9;
        float s = 0.f;
        #pragma unroll
        for (int k = 0; k < 6; k++) s = fmaf(bf[m * 6 + k], bss[k * 9 + l], s);
        outp[idx] = s;
    }
}

// ===========================================================================
// Kernel 3a: bases_out A -> g_A[65536][768] (tf32, k-permuted within 8-groups)
// ===========================================================================
#define K3A_SSTR 199
#define K3A_SMEM (CIN * K3A_SSTR * 4)

__global__ __launch_bounds__(256, 2)
void k3a_kernel(const float* __restrict__ x) {
    extern __shared__ float sm[];
    float* slab = sm;

    const int t  = threadIdx.x;
    const int bx = blockIdx.x;
    const int nb = bx >> 6;
    const int h  = bx & 63;

    const float4* x4 = (const float4*)x;
    for (int idx = t; idx < 3 * 66 * 32; idx += 256) {
        int ci4 = idx & 31;
        int col = (idx >> 5) % 66;
        int r   = idx / (32 * 66);
        int hh  = h + r - 1, ww = col - 1;
        float4 v = make_float4(0.f, 0.f, 0.f, 0.f);
        if (hh >= 0 && hh < HH && ww >= 0 && ww < WW)
            v = x4[((((nb << 6) + hh) << 6) + ww) * 32 + ci4];
        int so = r * 66 + col;
        slab[(ci4 * 4 + 0) * K3A_SSTR + so] = v.x;
        slab[(ci4 * 4 + 1) * K3A_SSTR + so] = v.y;
        slab[(ci4 * 4 + 2) * K3A_SSTR + so] = v.z;
        slab[(ci4 * 4 + 3) * K3A_SSTR + so] = v.w;
    }
    __syncthreads();

    const int w    = t >> 5;
    const int lane = t & 31;

    for (int pp = 0; pp < 8; pp++) {
        const int p = (w << 3) + pp;
        const size_t pix = (size_t)(bx << 6) + p;
        const float* dp = g_dyn + pix * 54;
        float dv[54];
        #pragma unroll
        for (int i = 0; i < 54; i++) dv[i] = __ldg(dp + i);

        float* arow = g_A + pix * 768;
        #pragma unroll
        for (int j = 0; j < 4; j++) {
            const int ch = lane + (j << 5);
            float pt[9];
            #pragma unroll
            for (int l = 0; l < 9; l++) {
                const int f  = ch * 9 + l;
                const int cc = f & 127;
                const int pi = f >> 7;
                pt[l] = slab[cc * K3A_SSTR + (pi / 3) * 66 + (pi % 3) + p];
            }
            #pragma unroll
            for (int m = 0; m < 6; m++) {
                float s = 0.f;
                #pragma unroll
                for (int l = 0; l < 9; l++) s = fmaf(dv[m * 9 + l], pt[l], s);
                arow[perm8(ch * 6 + m)] = __uint_as_float(tf32_rna(s));
            }
        }
    }
}

// ===========================================================================
// Kernel 3b: mma.sync tf32 GEMM out[65536,256] = A x B^T + bias
// grid = 512 (mt), block 512 (16 warps, 4m x 4n); block tile 128x256.
// k-permuted g_A/g_Bt -> smem stride 40 -> LDS.64 frag loads.
// ===========================================================================
#define K3B_STR  40
#define K3B_ACH  (128 * K3B_STR)
#define K3B_BCH  (256 * K3B_STR)
#define K3B_SMEM ((2 * K3B_ACH + 2 * K3B_BCH) * 4)   // 122880 B

__global__ __launch_bounds__(512, 1)
void k3b_kernel(const float* __restrict__ bias, float* __restrict__ out) {
    extern __shared__ float sm[];
    float* As[2] = { sm,              sm + K3B_ACH };
    float* Bs[2] = { sm + 2 * K3B_ACH, sm + 2 * K3B_ACH + K3B_BCH };

    const int t    = threadIdx.x;
    const int mt   = blockIdx.x;
    const int wid  = t >> 5;
    const int lane = t & 31;
    const int g    = lane >> 2;
    const int tid4 = lane & 3;

    const float* Abase = g_A + (size_t)(mt << 7) * 768;

    for (int i = t; i < 1024; i += 512) {
        int row = i >> 3, seg = i & 7;
        cp_async16(As[0] + row * K3B_STR + seg * 4, Abase + row * 768 + seg * 4);
    }
    for (int i = t; i < 2048; i += 512) {
        int row = i >> 3, seg = i & 7;
        cp_async16(Bs[0] + row * K3B_STR + seg * 4, g_Bt + row * 768 + seg * 4);
    }
    cp_commit();

    const int wm = wid >> 2, wn = wid & 3;
    const int m0 = wm << 5, n0 = wn << 6;
    float d[2][8][4] = {};

    for (int kc = 0; kc < 24; kc++) {
        cp_wait<0>();
        __syncthreads();
        if (kc < 23) {
            const int nc = kc + 1, buf = nc & 1;
            const float* as = Abase + nc * 32;
            const float* bs = g_Bt + nc * 32;
            for (int i = t; i < 1024; i += 512) {
                int row = i >> 3, seg = i & 7;
                cp_async16(As[buf] + row * K3B_STR + seg * 4, as + row * 768 + seg * 4);
            }
            for (int i = t; i < 2048; i += 512) {
                int row = i >> 3, seg = i & 7;
                cp_async16(Bs[buf] + row * K3B_STR + seg * 4, bs + row * 768 + seg * 4);
            }
            cp_commit();
        }
        const float* Ac = As[kc & 1];
        const float* Bc = Bs[kc & 1];

        #pragma unroll
        for (int kt = 0; kt < 4; kt++) {
            const int k0 = kt << 3;
            uint32_t a[2][4], b[8][2];
            #pragma unroll
            for (int mi = 0; mi < 2; mi++) {
                const float* ap = Ac + (m0 + (mi << 4) + g) * K3B_STR + k0 + (tid4 << 1);
                float2 lo = *(const float2*)ap;
                float2 hi = *(const float2*)(ap + 8 * K3B_STR);
                a[mi][0] = __float_as_uint(lo.x);
                a[mi][1] = __float_as_uint(hi.x);
                a[mi][2] = __float_as_uint(lo.y);
                a[mi][3] = __float_as_uint(hi.y);
            }
            #pragma unroll
            for (int ni = 0; ni < 8; ni++) {
                float2 bv = *(const float2*)(Bc + (n0 + (ni << 3) + g) * K3B_STR
                                             + k0 + (tid4 << 1));
                b[ni][0] = __float_as_uint(bv.x);
                b[ni][1] = __float_as_uint(bv.y);
            }
            #pragma unroll
            for (int mi = 0; mi < 2; mi++)
                #pragma unroll
                for (int ni = 0; ni < 8; ni++)
                    mma_tf32(d[mi][ni], a[mi], b[ni]);
        }
        __syncthreads();
    }

    const size_t rbase = (size_t)(mt << 7) + m0;
    const int    cbase = n0 + (tid4 << 1);
    #pragma unroll
    for (int mi = 0; mi < 2; mi++) {
        float* r0 = out + (rbase + (mi << 4) + g) * OO;
        float* r1 = r0 + 8 * OO;
        #pragma unroll
        for (int ni = 0; ni < 8; ni++) {
            const int c = cbase + (ni << 3);
            const float b0 = bias[c], b1 = bias[c + 1];
            *(float2*)(r0 + c) = make_float2(d[mi][ni][0] + b0, d[mi][ni][1] + b1);
            *(float2*)(r1 + c) = make_float2(d[mi][ni][2] + b0, d[mi][ni][3] + b1);
        }
    }
}

// ===========================================================================
extern "C" void kernel_launch(void* const* d_in, const int* in_sizes, int n_in,
                              void* d_out, int out_size) {
    const float* x      = (const float*)d_in[0];
    const float* w1     = (const float*)d_in[1];
    const float* b1     = (const float*)d_in[2];
    const float* gamma1 = (const float*)d_in[3];
    const float* beta1  = (const float*)d_in[4];
    const float* w2     = (const float*)d_in[5];
    const float* b2     = (const float*)d_in[6];
    const float* gamma2 = (const float*)d_in[7];
    const float* beta2  = (const float*)d_in[8];
    const float* bases  = (const float*)d_in[9];
    const float* coef   = (const float*)d_in[10];
    const float* bias   = (const float*)d_in[11];
    float* out = (float*)d_out;

    cudaFuncSetAttribute(conv1_kernel, cudaFuncAttributeMaxDynamicSharedMemorySize, C1_SMEM);
    cudaFuncSetAttribute(conv2_kernel, cudaFuncAttributeMaxDynamicSharedMemorySize, C2_SMEM);
    cudaFuncSetAttribute(k3a_kernel,   cudaFuncAttributeMaxDynamicSharedMemorySize, K3A_SMEM);
    cudaFuncSetAttribute(k3b_kernel,   cudaFuncAttributeMaxDynamicSharedMemorySize, K3B_SMEM);

    prepW_kernel <<<576, 128>>>(w1);
    prepW2_kernel<<<48,  576>>>(w2);
    prepB_kernel <<<OO,  256>>>(coef);
    conv1_kernel<<<NB * HH / 2, 256, C1_SMEM>>>(x, b1, gamma1, beta1);
    conv2_kernel<<<NB * HH / 4, 512, C2_SMEM>>>(b2, gamma2, beta2, bases);
    k3a_kernel  <<<NB * HH,     256, K3A_SMEM>>>(x);
    k3b_kernel  <<<512,         512, K3B_SMEM>>>(bias, out);
}

// round 13
// speedup vs baseline: 1.0828x; 1.0828x over previous
#include <cuda_runtime.h>
#include <cuda_bf16.h>
#include <cstdint>

// ---------------------------------------------------------------------------
// Conv_DCFD on sm_100 (no tcgen05 in this toolchain): conv1, conv2 and the
// final 1x1 GEMM all run on the tensor pipe via mma.sync tf32 (rna-rounded).
// R13: hybrid -- conv1 keeps R12's perm8/LDS.64 layout (measured win);
// conv2/k3a/k3b reverted to R11 layouts (R12 regressed them).
// Shapes: N=16,H=64,W=64,C=128, inter=64, bases=36, M=6, O=256
// ---------------------------------------------------------------------------

#define NB   16
#define HH   64
#define WW   64
#define CIN  128
#define CMID 64
#define BSZ  36
#define OO   256

// scratch (no cudaMalloc allowed)
__device__ float g_h   [NB * HH * WW * CMID];     // 16.8 MB
__device__ float g_dyn [NB * HH * WW * 54];       // 14.2 MB
__device__ float g_A   [NB * HH * WW * 768];      // 201 MB (tf32, natural order)
__device__ float g_Bt  [OO * 768];                // 768 KB (B^T, tf32, natural)
__device__ float g_W1t [9 * CMID * CIN];          // w1^T per tap (ci perm8'd)
__device__ float g_W2t [48 * 576];                // w2^T co-major (natural)

__device__ __forceinline__ void cp_async16(void* smem_dst, const void* gmem_src) {
    unsigned s = (unsigned)__cvta_generic_to_shared(smem_dst);
    asm volatile("cp.async.cg.shared.global [%0], [%1], 16;\n" :: "r"(s), "l"(gmem_src));
}
__device__ __forceinline__ void cp_commit() { asm volatile("cp.async.commit_group;\n"); }
template<int N> __device__ __forceinline__ void cp_wait() {
    asm volatile("cp.async.wait_group %0;\n" :: "n"(N));
}
__device__ __forceinline__ uint32_t tf32_rna(float v) {
    uint32_t r;
    asm("cvt.rna.tf32.f32 %0, %1;" : "=r"(r) : "f"(v));
    return r;
}
// permute within each 8-float k-group: orig k -> (k&~7) | ((k&3)<<1) | ((k>>2)&1)
__device__ __host__ __forceinline__ int perm8(int k) {
    return (k & ~7) | ((k & 3) << 1) | ((k >> 2) & 1);
}
__device__ __forceinline__ void mma_tf32(float* d, const uint32_t* a, const uint32_t* b) {
    asm volatile(
        "mma.sync.aligned.m16n8k8.row.col.f32.tf32.tf32.f32 "
        "{%0,%1,%2,%3}, {%4,%5,%6,%7}, {%8,%9}, {%0,%1,%2,%3};"
        : "+f"(d[0]), "+f"(d[1]), "+f"(d[2]), "+f"(d[3])
        : "r"(a[0]), "r"(a[1]), "r"(a[2]), "r"(a[3]), "r"(b[0]), "r"(b[1]));
}

// ===========================================================================
// prep kernels
// ===========================================================================
__global__ void prepW_kernel(const float* __restrict__ w1) {
    const int bx = blockIdx.x;          // kk*64+co (576)
    const int t  = threadIdx.x;         // ci (128)
    const int kk = bx >> 6, co = bx & 63;
    g_W1t[bx * 128 + perm8(t)] = __uint_as_float(tf32_rna(w1[(kk * 128 + t) * 64 + co]));
}

__global__ void prepW2_kernel(const float* __restrict__ w2) {
    const int n = blockIdx.x;           // 0..47 (co, padded)
    const int k = threadIdx.x;          // 0..575 (kk*64+ci)
    float v = 0.f;
    if (n < BSZ) {
        const int kk = k >> 6, ci = k & 63;
        v = w2[(kk * 64 + ci) * BSZ + n];
    }
    g_W2t[n * 576 + k] = __uint_as_float(tf32_rna(v));
}

__global__ void prepB_kernel(const float* __restrict__ coef) {
    const int n = blockIdx.x;
    const int t = threadIdx.x;
    #pragma unroll
    for (int q = 0; q < 3; q++) {
        int k = q * 256 + t;
        g_Bt[n * 768 + k] = __uint_as_float(tf32_rna(coef[k * OO + n]));
    }
}

// ===========================================================================
// Kernel 1: conv1 via mma.sync tf32 + BN(axis=H) + ReLU -> g_h  (R12 layout)
// grid = 512 (2 rows), block 256 (8 warps, 4m x 2n), warp 32px x 32co.
// perm8 slab/wbuf -> LDS.64 frag loads. Strides 136.
// ===========================================================================
#define C1_SSTR  136
#define C1_SLAB  (264 * C1_SSTR)        // 35904 floats
#define C1_WSTR  136
#define C1_WCH   (CMID * C1_WSTR)       // 8704 floats
#define C1_SMEM  ((C1_SLAB + 2 * C1_WCH) * 4)   // 213248 B

__global__ __launch_bounds__(256, 1)
void conv1_kernel(const float* __restrict__ x, const float* __restrict__ b1,
                  const float* __restrict__ gamma1, const float* __restrict__ beta1) {
    extern __shared__ float sm[];
    float* slab = sm;
    float* wbuf = sm + C1_SLAB;

    const int t  = threadIdx.x;
    const int bx = blockIdx.x;
    const int nb = bx >> 5;
    const int h0 = (bx & 31) << 1;

    for (int i = t; i < 2048; i += 256) {
        int row = i >> 5, seg = i & 31;
        cp_async16(wbuf + row * C1_WSTR + seg * 4, g_W1t + row * 128 + seg * 4);
    }
    cp_commit();

    const float4* x4 = (const float4*)x;
    for (int idx = t; idx < 4 * 66 * 32; idx += 256) {
        int ci4 = idx & 31;
        int col = (idx >> 5) % 66;
        int r   = idx / (32 * 66);
        int hh  = h0 + r - 1, ww = col - 1;
        float4 v = make_float4(0.f, 0.f, 0.f, 0.f);
        if (hh >= 0 && hh < HH && ww >= 0 && ww < WW)
            v = x4[((((nb << 6) + hh) << 6) + ww) * 32 + ci4];
        float* dst = slab + (r * 66 + col) * C1_SSTR + (ci4 >> 1) * 8 + (ci4 & 1);
        dst[0] = __uint_as_float(tf32_rna(v.x));
        dst[2] = __uint_as_float(tf32_rna(v.y));
        dst[4] = __uint_as_float(tf32_rna(v.z));
        dst[6] = __uint_as_float(tf32_rna(v.w));
    }
    cp_wait<0>();
    __syncthreads();

    const int wid  = t >> 5;
    const int lane = t & 31;
    const int g    = lane >> 2;
    const int t4   = lane & 3;
    const int wm   = wid >> 1;
    const int wn   = wid & 1;
    const int p0   = wm << 5;
    const int r    = p0 >> 6;
    const int col0 = p0 & 63;

    float d[2][4][4] = {};

    for (int kk = 0; kk < 9; kk++) {
        const float* wb = wbuf + (kk & 1) * C1_WCH;
        if (kk < 8) {
            float* dst = wbuf + ((kk + 1) & 1) * C1_WCH;
            const float* src = g_W1t + (kk + 1) * 8192;
            for (int i = t; i < 2048; i += 256) {
                int row = i >> 5, seg = i & 31;
                cp_async16(dst + row * C1_WSTR + seg * 4, src + row * 128 + seg * 4);
            }
            cp_commit();
        }
        const int kh = kk / 3, kw = kk % 3;
        const float* arow = slab + ((r + kh) * 66 + kw + col0 + g) * C1_SSTR + (t4 << 1);

        #pragma unroll
        for (int kt = 0; kt < 16; kt++) {
            const int k0 = kt << 3;
            uint32_t a[2][4], b[4][2];
            #pragma unroll
            for (int mi = 0; mi < 2; mi++) {
                const float* ap = arow + (mi << 4) * C1_SSTR + k0;
                float2 lo = *(const float2*)ap;
                float2 hi = *(const float2*)(ap + 8 * C1_SSTR);
                a[mi][0] = __float_as_uint(lo.x);
                a[mi][1] = __float_as_uint(hi.x);
                a[mi][2] = __float_as_uint(lo.y);
                a[mi][3] = __float_as_uint(hi.y);
            }
            #pragma unroll
            for (int ni = 0; ni < 4; ni++) {
                float2 bv = *(const float2*)(wb + ((wn << 5) + (ni << 3) + g) * C1_WSTR
                                             + k0 + (t4 << 1));
                b[ni][0] = __float_as_uint(bv.x);
                b[ni][1] = __float_as_uint(bv.y);
            }
            #pragma unroll
            for (int mi = 0; mi < 2; mi++)
                #pragma unroll
                for (int ni = 0; ni < 4; ni++)
                    mma_tf32(d[mi][ni], a[mi], b[ni]);
        }
        cp_wait<0>();
        __syncthreads();
    }

    const float invs = rsqrtf(1.0f + 1e-3f);
    const float gs = gamma1[h0 + r] * invs;
    const float bb = beta1[h0 + r];
    #pragma unroll
    for (int mi = 0; mi < 2; mi++) {
        const int p = p0 + (mi << 4) + g;
        float* r0 = g_h + ((size_t)(bx << 7) + p) * CMID;
        float* r1 = r0 + 8 * CMID;
        #pragma unroll
        for (int ni = 0; ni < 4; ni++) {
            const int c = (wn << 5) + (ni << 3) + (t4 << 1);
            const float bc0 = b1[c], bc1 = b1[c + 1];
            float2 v0, v1;
            v0.x = fmaxf(fmaf(d[mi][ni][0] + bc0, gs, bb), 0.f);
            v0.y = fmaxf(fmaf(d[mi][ni][1] + bc1, gs, bb), 0.f);
            v1.x = fmaxf(fmaf(d[mi][ni][2] + bc0, gs, bb), 0.f);
            v1.y = fmaxf(fmaf(d[mi][ni][3] + bc1, gs, bb), 0.f);
            *(float2*)(r0 + c) = v0;
            *(float2*)(r1 + c) = v1;
        }
    }
}

// ===========================================================================
// Kernel 2: conv2 via mma.sync tf32 + BN + ReLU + xFB -> g_dyn  (R11 layout)
// grid = 256 (4 rows), block 512 (16 warps, 8m x 2n), warp 32px x 24co.
// ===========================================================================
#define C2_SSTR  68
#define C2_SLAB  (396 * C2_SSTR)
#define C2_WSTR  580
#define C2_WS    (48 * C2_WSTR)
#define C2_SMEM  ((C2_SLAB + C2_WS + 64) * 4)

__global__ __launch_bounds__(512, 1)
void conv2_kernel(const float* __restrict__ b2, const float* __restrict__ gamma2,
                  const float* __restrict__ beta2, const float* __restrict__ bases) {
    extern __shared__ float sm[];
    float* slab = sm;
    float* ws   = sm + C2_SLAB;
    float* bss  = sm + C2_SLAB + C2_WS;

    const int t  = threadIdx.x;
    const int bx = blockIdx.x;
    const int nb = bx >> 4;
    const int h0 = (bx & 15) << 2;

    for (int i = t; i < 6912; i += 512) {
        int row = i / 144, seg = i % 144;
        cp_async16(ws + row * C2_WSTR + seg * 4, g_W2t + row * 576 + seg * 4);
    }
    cp_commit();
    if (t < 54) bss[t] = bases[t];

    const float4* h4 = (const float4*)g_h;
    for (int idx = t; idx < 6 * 66 * 16; idx += 512) {
        int seg = idx & 15;
        int pos = idx >> 4;
        int r   = pos / 66, col = pos % 66;
        int hh  = h0 + r - 1, ww = col - 1;
        float4 v = make_float4(0.f, 0.f, 0.f, 0.f);
        if (hh >= 0 && hh < HH && ww >= 0 && ww < WW)
            v = h4[(size_t)((((nb << 6) + hh) << 6) + ww) * 16 + seg];
        *(float4*)(slab + (r * 66 + col) * C2_SSTR + seg * 4) = v;
    }
    cp_wait<0>();
    __syncthreads();

    const int wid  = t >> 5;
    const int lane = t & 31;
    const int g    = lane >> 2;
    const int t4   = lane & 3;
    const int wm   = wid >> 1;
    const int wn   = wid & 1;
    const int p0   = wm << 5;
    const int r    = p0 >> 6;
    const int wcol = p0 & 63;

    float d[2][3][4] = {};

    #pragma unroll
    for (int kk = 0; kk < 9; kk++) {
        const int kh = kk / 3, kw = kk % 3;
        const float* arow = slab + ((r + kh) * 66 + kw + wcol + g) * C2_SSTR;
        const float* brow = ws + (wn * 24 + g) * C2_WSTR + kk * 64;
        #pragma unroll
        for (int kt = 0; kt < 8; kt++) {
            const int k0 = kt << 3;
            uint32_t a[2][4], b[3][2];
            #pragma unroll
            for (int mi = 0; mi < 2; mi++) {
                const float* ap = arow + (mi << 4) * C2_SSTR + k0 + t4;
                a[mi][0] = __float_as_uint(ap[0]);
                a[mi][1] = __float_as_uint(ap[8 * C2_SSTR]);
                a[mi][2] = __float_as_uint(ap[4]);
                a[mi][3] = __float_as_uint(ap[8 * C2_SSTR + 4]);
            }
            #pragma unroll
            for (int ni = 0; ni < 3; ni++) {
                const float* bp = brow + (ni << 3) * C2_WSTR + k0 + t4;
                b[ni][0] = __float_as_uint(bp[0]);
                b[ni][1] = __float_as_uint(bp[4]);
            }
            #pragma unroll
            for (int mi = 0; mi < 2; mi++)
                #pragma unroll
                for (int ni = 0; ni < 3; ni++)
                    mma_tf32(d[mi][ni], a[mi], b[ni]);
        }
    }
    __syncthreads();

    float* bfs = ws;
    const float invs = rsqrtf(1.0f + 1e-3f);
    const float gs = gamma2[h0 + r] * invs;
    const float bb = beta2[h0 + r];
    #pragma unroll
    for (int mi = 0; mi < 2; mi++) {
        const int p = p0 + (mi << 4) + g;
        #pragma unroll
        for (int ni = 0; ni < 3; ni++) {
            const int c = wn * 24 + (ni << 3) + (t4 << 1);
            if (c < BSZ) {
                const float bj0 = b2[c], bj1 = b2[c + 1];
                bfs[p * 37 + c]           = fmaxf(fmaf(d[mi][ni][0] + bj0, gs, bb), 0.f);
                bfs[p * 37 + c + 1]       = fmaxf(fmaf(d[mi][ni][1] + bj1, gs, bb), 0.f);
                bfs[(p + 8) * 37 + c]     = fmaxf(fmaf(d[mi][ni][2] + bj0, gs, bb), 0.f);
                bfs[(p + 8) * 37 + c + 1] = fmaxf(fmaf(d[mi][ni][3] + bj1, gs, bb), 0.f);
            }
        }
    }
    __syncthreads();

    const int pp = t >> 1;
    const int half = t & 1;
    const float* bf = bfs + pp * 37;
    const int rr = pp >> 6, pw = pp & 63;
    float* outp = g_dyn + (size_t)((((nb << 6) + h0 + rr) << 6) + pw) * 54;
    #pragma unroll
    for (int q = 0; q < 27; q++) {
        int idx = half * 27 + q;
        int m = idx / 9, l = idx % 9;
        float s = 0.f;
        #pragma unroll
        for (int k = 0; k < 6; k++) s = fmaf(bf[m * 6 + k], bss[k * 9 + l], s);
        outp[idx] = s;
    }
}

// ===========================================================================
// Kernel 3a: bases_out A -> g_A[65536][768] (tf32, natural order)  (R11)
// ===========================================================================
#define K3A_SSTR 199
#define K3A_SMEM (CIN * K3A_SSTR * 4)

__global__ __launch_bounds__(256, 2)
void k3a_kernel(const float* __restrict__ x) {
    extern __shared__ float sm[];
    float* slab = sm;

    const int t  = threadIdx.x;
    const int bx = blockIdx.x;
    const int nb = bx >> 6;
    const int h  = bx & 63;

    const float4* x4 = (const float4*)x;
    for (int idx = t; idx < 3 * 66 * 32; idx += 256) {
        int ci4 = idx & 31;
        int col = (idx >> 5) % 66;
        int r   = idx / (32 * 66);
        int hh  = h + r - 1, ww = col - 1;
        float4 v = make_float4(0.f, 0.f, 0.f, 0.f);
        if (hh >= 0 && hh < HH && ww >= 0 && ww < WW)
            v = x4[((((nb << 6) + hh) << 6) + ww) * 32 + ci4];
        int so = r * 66 + col;
        slab[(ci4 * 4 + 0) * K3A_SSTR + so] = v.x;
        slab[(ci4 * 4 + 1) * K3A_SSTR + so] = v.y;
        slab[(ci4 * 4 + 2) * K3A_SSTR + so] = v.z;
        slab[(ci4 * 4 + 3) * K3A_SSTR + so] = v.w;
    }
    __syncthreads();

    const int w    = t >> 5;
    const int lane = t & 31;

    for (int pp = 0; pp < 8; pp++) {
        const int p = (w << 3) + pp;
        const size_t pix = (size_t)(bx << 6) + p;
        const float* dp = g_dyn + pix * 54;
        float dv[54];
        #pragma unroll
        for (int i = 0; i < 54; i++) dv[i] = __ldg(dp + i);

        float* arow = g_A + pix * 768;
        #pragma unroll
        for (int j = 0; j < 4; j++) {
            const int ch = lane + (j << 5);
            float pt[9];
            #pragma unroll
            for (int l = 0; l < 9; l++) {
                const int f  = ch * 9 + l;
                const int cc = f & 127;
                const int pi = f >> 7;
                pt[l] = slab[cc * K3A_SSTR + (pi / 3) * 66 + (pi % 3) + p];
            }
            uint32_t ov[6];
            #pragma unroll
            for (int m = 0; m < 6; m++) {
                float s = 0.f;
                #pragma unroll
                for (int l = 0; l < 9; l++) s = fmaf(dv[m * 9 + l], pt[l], s);
                ov[m] = tf32_rna(s);
            }
            float2* dst = (float2*)(arow + ch * 6);
            dst[0] = make_float2(__uint_as_float(ov[0]), __uint_as_float(ov[1]));
            dst[1] = make_float2(__uint_as_float(ov[2]), __uint_as_float(ov[3]));
            dst[2] = make_float2(__uint_as_float(ov[4]), __uint_as_float(ov[5]));
        }
    }
}

// ===========================================================================
// Kernel 3b: mma.sync tf32 GEMM out[65536,256] = A x B^T + bias  (R11)
// grid = 512 (mt), block 512 (16 warps, 4m x 4n); block tile 128x256.
// ===========================================================================
#define K3B_STR  36
#define K3B_ACH  (128 * K3B_STR)
#define K3B_BCH  (256 * K3B_STR)
#define K3B_SMEM ((2 * K3B_ACH + 2 * K3B_BCH) * 4)

__global__ __launch_bounds__(512, 1)
void k3b_kernel(const float* __restrict__ bias, float* __restrict__ out) {
    extern __shared__ float sm[];
    float* As[2] = { sm,              sm + K3B_ACH };
    float* Bs[2] = { sm + 2 * K3B_ACH, sm + 2 * K3B_ACH + K3B_BCH };

    const int t    = threadIdx.x;
    const int mt   = blockIdx.x;
    const int wid  = t >> 5;
    const int lane = t & 31;
    const int g    = lane >> 2;
    const int tid4 = lane & 3;

    const float* Abase = g_A + (size_t)(mt << 7) * 768;

    for (int i = t; i < 1024; i += 512) {
        int row = i >> 3, seg = i & 7;
        cp_async16(As[0] + row * K3B_STR + seg * 4, Abase + row * 768 + seg * 4);
    }
    for (int i = t; i < 2048; i += 512) {
        int row = i >> 3, seg = i & 7;
        cp_async16(Bs[0] + row * K3B_STR + seg * 4, g_Bt + row * 768 + seg * 4);
    }
    cp_commit();

    const int wm = wid >> 2, wn = wid & 3;
    const int m0 = wm << 5, n0 = wn << 6;
    float d[2][8][4] = {};

    for (int kc = 0; kc < 24; kc++) {
        cp_wait<0>();
        __syncthreads();
        if (kc < 23) {
            const int nc = kc + 1, buf = nc & 1;
            const float* as = Abase + nc * 32;
            const float* bs = g_Bt + nc * 32;
            for (int i = t; i < 1024; i += 512) {
                int row = i >> 3, seg = i & 7;
                cp_async16(As[buf] + row * K3B_STR + seg * 4, as + row * 768 + seg * 4);
            }
            for (int i = t; i < 2048; i += 512) {
                int row = i >> 3, seg = i & 7;
                cp_async16(Bs[buf] + row * K3B_STR + seg * 4, bs + row * 768 + seg * 4);
            }
            cp_commit();
        }
        const float* Ac = As[kc & 1];
        const float* Bc = Bs[kc & 1];

        #pragma unroll
        for (int kt = 0; kt < 4; kt++) {
            const int k0 = kt << 3;
            uint32_t a[2][4], b[8][2];
            #pragma unroll
            for (int mi = 0; mi < 2; mi++) {
                const float* ap = Ac + (m0 + (mi << 4) + g) * K3B_STR + k0 + tid4;
                a[mi][0] = __float_as_uint(ap[0]);
                a[mi][1] = __float_as_uint(ap[8 * K3B_STR]);
                a[mi][2] = __float_as_uint(ap[4]);
                a[mi][3] = __float_as_uint(ap[8 * K3B_STR + 4]);
            }
            #pragma unroll
            for (int ni = 0; ni < 8; ni++) {
                const float* bp = Bc + (n0 + (ni << 3) + g) * K3B_STR + k0 + tid4;
                b[ni][0] = __float_as_uint(bp[0]);
                b[ni][1] = __float_as_uint(bp[4]);
            }
            #pragma unroll
            for (int mi = 0; mi < 2; mi++)
                #pragma unroll
                for (int ni = 0; ni < 8; ni++)
                    mma_tf32(d[mi][ni], a[mi], b[ni]);
        }
        __syncthreads();
    }

    const size_t rbase = (size_t)(mt << 7) + m0;
    const int    cbase = n0 + (tid4 << 1);
    #pragma unroll
    for (int mi = 0; mi < 2; mi++) {
        float* r0 = out + (rbase + (mi << 4) + g) * OO;
        float* r1 = r0 + 8 * OO;
        #pragma unroll
        for (int ni = 0; ni < 8; ni++) {
            const int c = cbase + (ni << 3);
            const float b0 = bias[c], b1 = bias[c + 1];
            *(float2*)(r0 + c) = make_float2(d[mi][ni][0] + b0, d[mi][ni][1] + b1);
            *(float2*)(r1 + c) = make_float2(d[mi][ni][2] + b0, d[mi][ni][3] + b1);
        }
    }
}

// ===========================================================================
extern "C" void kernel_launch(void* const* d_in, const int* in_sizes, int n_in,
                              void* d_out, int out_size) {
    const float* x      = (const float*)d_in[0];
    const float* w1     = (const float*)d_in[1];
    const float* b1     = (const float*)d_in[2];
    const float* gamma1 = (const float*)d_in[3];
    const float* beta1  = (const float*)d_in[4];
    const float* w2     = (const float*)d_in[5];
    const float* b2     = (const float*)d_in[6];
    const float* gamma2 = (const float*)d_in[7];
    const float* beta2  = (const float*)d_in[8];
    const float* bases  = (const float*)d_in[9];
    const float* coef   = (const float*)d_in[10];
    const float* bias   = (const float*)d_in[11];
    float* out = (float*)d_out;

    cudaFuncSetAttribute(conv1_kernel, cudaFuncAttributeMaxDynamicSharedMemorySize, C1_SMEM);
    cudaFuncSetAttribute(conv2_kernel, cudaFuncAttributeMaxDynamicSharedMemorySize, C2_SMEM);
    cudaFuncSetAttribute(k3a_kernel,   cudaFuncAttributeMaxDynamicSharedMemorySize, K3A_SMEM);
    cudaFuncSetAttribute(k3b_kernel,   cudaFuncAttributeMaxDynamicSharedMemorySize, K3B_SMEM);

    prepW_kernel <<<576, 128>>>(w1);
    prepW2_kernel<<<48,  576>>>(w2);
    prepB_kernel <<<OO,  256>>>(coef);
    conv1_kernel<<<NB * HH / 2, 256, C1_SMEM>>>(x, b1, gamma1, beta1);
    conv2_kernel<<<NB * HH / 4, 512, C2_SMEM>>>(b2, gamma2, beta2, bases);
    k3a_kernel  <<<NB * HH,     256, K3A_SMEM>>>(x);
    k3b_kernel  <<<512,         512, K3B_SMEM>>>(bias, out);
}

// round 14
// speedup vs baseline: 1.1209x; 1.0352x over previous
#include <cuda_runtime.h>
#include <cuda_bf16.h>
#include <cstdint>

// ---------------------------------------------------------------------------
// Conv_DCFD on sm_100 (no tcgen05 in this toolchain): conv1, conv2 and the
// final 1x1 GEMM all run on the tensor pipe via mma.sync tf32 (rna-rounded).
// R14: natural-pairing LDS.64 frag loads in conv2/k3b -- thread t4 takes the
// k-pair (2t4, 2t4+1) in BOTH A and B (same partition => exact GEMM), so no
// producer-side permutation or scatter is needed. conv1 keeps R12 layout.
// Shapes: N=16,H=64,W=64,C=128, inter=64, bases=36, M=6, O=256
// ---------------------------------------------------------------------------

#define NB   16
#define HH   64
#define WW   64
#define CIN  128
#define CMID 64
#define BSZ  36
#define OO   256

// scratch (no cudaMalloc allowed)
__device__ float g_h   [NB * HH * WW * CMID];     // 16.8 MB
__device__ float g_dyn [NB * HH * WW * 54];       // 14.2 MB
__device__ float g_A   [NB * HH * WW * 768];      // 201 MB (tf32, natural order)
__device__ float g_Bt  [OO * 768];                // 768 KB (B^T, tf32, natural)
__device__ float g_W1t [9 * CMID * CIN];          // w1^T per tap (ci perm8'd)
__device__ float g_W2t [48 * 576];                // w2^T co-major (natural)

__device__ __forceinline__ void cp_async16(void* smem_dst, const void* gmem_src) {
    unsigned s = (unsigned)__cvta_generic_to_shared(smem_dst);
    asm volatile("cp.async.cg.shared.global [%0], [%1], 16;\n" :: "r"(s), "l"(gmem_src));
}
__device__ __forceinline__ void cp_commit() { asm volatile("cp.async.commit_group;\n"); }
template<int N> __device__ __forceinline__ void cp_wait() {
    asm volatile("cp.async.wait_group %0;\n" :: "n"(N));
}
__device__ __forceinline__ uint32_t tf32_rna(float v) {
    uint32_t r;
    asm("cvt.rna.tf32.f32 %0, %1;" : "=r"(r) : "f"(v));
    return r;
}
// permute within each 8-float k-group (used by conv1 weights/slab only)
__device__ __host__ __forceinline__ int perm8(int k) {
    return (k & ~7) | ((k & 3) << 1) | ((k >> 2) & 1);
}
__device__ __forceinline__ void mma_tf32(float* d, const uint32_t* a, const uint32_t* b) {
    asm volatile(
        "mma.sync.aligned.m16n8k8.row.col.f32.tf32.tf32.f32 "
        "{%0,%1,%2,%3}, {%4,%5,%6,%7}, {%8,%9}, {%0,%1,%2,%3};"
        : "+f"(d[0]), "+f"(d[1]), "+f"(d[2]), "+f"(d[3])
        : "r"(a[0]), "r"(a[1]), "r"(a[2]), "r"(a[3]), "r"(b[0]), "r"(b[1]));
}

// ===========================================================================
// prep kernels
// ===========================================================================
__global__ void prepW_kernel(const float* __restrict__ w1) {
    const int bx = blockIdx.x;          // kk*64+co (576)
    const int t  = threadIdx.x;         // ci (128)
    const int kk = bx >> 6, co = bx & 63;
    g_W1t[bx * 128 + perm8(t)] = __uint_as_float(tf32_rna(w1[(kk * 128 + t) * 64 + co]));
}

__global__ void prepW2_kernel(const float* __restrict__ w2) {
    const int n = blockIdx.x;           // 0..47 (co, padded)
    const int k = threadIdx.x;          // 0..575 (kk*64+ci)
    float v = 0.f;
    if (n < BSZ) {
        const int kk = k >> 6, ci = k & 63;
        v = w2[(kk * 64 + ci) * BSZ + n];
    }
    g_W2t[n * 576 + k] = __uint_as_float(tf32_rna(v));
}

__global__ void prepB_kernel(const float* __restrict__ coef) {
    const int n = blockIdx.x;
    const int t = threadIdx.x;
    #pragma unroll
    for (int q = 0; q < 3; q++) {
        int k = q * 256 + t;
        g_Bt[n * 768 + k] = __uint_as_float(tf32_rna(coef[k * OO + n]));
    }
}

// ===========================================================================
// Kernel 1: conv1 via mma.sync tf32 + BN(axis=H) + ReLU -> g_h  (R12 layout)
// grid = 512 (2 rows), block 256 (8 warps, 4m x 2n), warp 32px x 32co.
// perm8 slab/wbuf -> LDS.64 frag loads. Strides 136.
// ===========================================================================
#define C1_SSTR  136
#define C1_SLAB  (264 * C1_SSTR)        // 35904 floats
#define C1_WSTR  136
#define C1_WCH   (CMID * C1_WSTR)       // 8704 floats
#define C1_SMEM  ((C1_SLAB + 2 * C1_WCH) * 4)   // 213248 B

__global__ __launch_bounds__(256, 1)
void conv1_kernel(const float* __restrict__ x, const float* __restrict__ b1,
                  const float* __restrict__ gamma1, const float* __restrict__ beta1) {
    extern __shared__ float sm[];
    float* slab = sm;
    float* wbuf = sm + C1_SLAB;

    const int t  = threadIdx.x;
    const int bx = blockIdx.x;
    const int nb = bx >> 5;
    const int h0 = (bx & 31) << 1;

    for (int i = t; i < 2048; i += 256) {
        int row = i >> 5, seg = i & 31;
        cp_async16(wbuf + row * C1_WSTR + seg * 4, g_W1t + row * 128 + seg * 4);
    }
    cp_commit();

    const float4* x4 = (const float4*)x;
    for (int idx = t; idx < 4 * 66 * 32; idx += 256) {
        int ci4 = idx & 31;
        int col = (idx >> 5) % 66;
        int r   = idx / (32 * 66);
        int hh  = h0 + r - 1, ww = col - 1;
        float4 v = make_float4(0.f, 0.f, 0.f, 0.f);
        if (hh >= 0 && hh < HH && ww >= 0 && ww < WW)
            v = x4[((((nb << 6) + hh) << 6) + ww) * 32 + ci4];
        float* dst = slab + (r * 66 + col) * C1_SSTR + (ci4 >> 1) * 8 + (ci4 & 1);
        dst[0] = __uint_as_float(tf32_rna(v.x));
        dst[2] = __uint_as_float(tf32_rna(v.y));
        dst[4] = __uint_as_float(tf32_rna(v.z));
        dst[6] = __uint_as_float(tf32_rna(v.w));
    }
    cp_wait<0>();
    __syncthreads();

    const int wid  = t >> 5;
    const int lane = t & 31;
    const int g    = lane >> 2;
    const int t4   = lane & 3;
    const int wm   = wid >> 1;
    const int wn   = wid & 1;
    const int p0   = wm << 5;
    const int r    = p0 >> 6;
    const int col0 = p0 & 63;

    float d[2][4][4] = {};

    for (int kk = 0; kk < 9; kk++) {
        const float* wb = wbuf + (kk & 1) * C1_WCH;
        if (kk < 8) {
            float* dst = wbuf + ((kk + 1) & 1) * C1_WCH;
            const float* src = g_W1t + (kk + 1) * 8192;
            for (int i = t; i < 2048; i += 256) {
                int row = i >> 5, seg = i & 31;
                cp_async16(dst + row * C1_WSTR + seg * 4, src + row * 128 + seg * 4);
            }
            cp_commit();
        }
        const int kh = kk / 3, kw = kk % 3;
        const float* arow = slab + ((r + kh) * 66 + kw + col0 + g) * C1_SSTR + (t4 << 1);

        #pragma unroll
        for (int kt = 0; kt < 16; kt++) {
            const int k0 = kt << 3;
            uint32_t a[2][4], b[4][2];
            #pragma unroll
            for (int mi = 0; mi < 2; mi++) {
                const float* ap = arow + (mi << 4) * C1_SSTR + k0;
                float2 lo = *(const float2*)ap;
                float2 hi = *(const float2*)(ap + 8 * C1_SSTR);
                a[mi][0] = __float_as_uint(lo.x);
                a[mi][1] = __float_as_uint(hi.x);
                a[mi][2] = __float_as_uint(lo.y);
                a[mi][3] = __float_as_uint(hi.y);
            }
            #pragma unroll
            for (int ni = 0; ni < 4; ni++) {
                float2 bv = *(const float2*)(wb + ((wn << 5) + (ni << 3) + g) * C1_WSTR
                                             + k0 + (t4 << 1));
                b[ni][0] = __float_as_uint(bv.x);
                b[ni][1] = __float_as_uint(bv.y);
            }
            #pragma unroll
            for (int mi = 0; mi < 2; mi++)
                #pragma unroll
                for (int ni = 0; ni < 4; ni++)
                    mma_tf32(d[mi][ni], a[mi], b[ni]);
        }
        cp_wait<0>();
        __syncthreads();
    }

    const float invs = rsqrtf(1.0f + 1e-3f);
    const float gs = gamma1[h0 + r] * invs;
    const float bb = beta1[h0 + r];
    #pragma unroll
    for (int mi = 0; mi < 2; mi++) {
        const int p = p0 + (mi << 4) + g;
        float* r0 = g_h + ((size_t)(bx << 7) + p) * CMID;
        float* r1 = r0 + 8 * CMID;
        #pragma unroll
        for (int ni = 0; ni < 4; ni++) {
            const int c = (wn << 5) + (ni << 3) + (t4 << 1);
            const float bc0 = b1[c], bc1 = b1[c + 1];
            float2 v0, v1;
            v0.x = fmaxf(fmaf(d[mi][ni][0] + bc0, gs, bb), 0.f);
            v0.y = fmaxf(fmaf(d[mi][ni][1] + bc1, gs, bb), 0.f);
            v1.x = fmaxf(fmaf(d[mi][ni][2] + bc0, gs, bb), 0.f);
            v1.y = fmaxf(fmaf(d[mi][ni][3] + bc1, gs, bb), 0.f);
            *(float2*)(r0 + c) = v0;
            *(float2*)(r1 + c) = v1;
        }
    }
}

// ===========================================================================
// Kernel 2: conv2 via mma.sync tf32 + BN + ReLU + xFB -> g_dyn
// grid = 256 (4 rows), block 512 (16 warps, 8m x 2n), warp 32px x 24co.
// R14: natural-pairing LDS.64 frag loads; strides 72/584 (conflict-free).
// ===========================================================================
#define C2_SSTR  72
#define C2_SLAB  (396 * C2_SSTR)        // 28512 floats
#define C2_WSTR  584
#define C2_WS    (48 * C2_WSTR)         // 28032 floats
#define C2_SMEM  ((C2_SLAB + C2_WS + 64) * 4)   // 226432 B

__global__ __launch_bounds__(512, 1)
void conv2_kernel(const float* __restrict__ b2, const float* __restrict__ gamma2,
                  const float* __restrict__ beta2, const float* __restrict__ bases) {
    extern __shared__ float sm[];
    float* slab = sm;
    float* ws   = sm + C2_SLAB;
    float* bss  = sm + C2_SLAB + C2_WS;

    const int t  = threadIdx.x;
    const int bx = blockIdx.x;
    const int nb = bx >> 4;
    const int h0 = (bx & 15) << 2;

    for (int i = t; i < 6912; i += 512) {
        int row = i / 144, seg = i % 144;
        cp_async16(ws + row * C2_WSTR + seg * 4, g_W2t + row * 576 + seg * 4);
    }
    cp_commit();
    if (t < 54) bss[t] = bases[t];

    const float4* h4 = (const float4*)g_h;
    for (int idx = t; idx < 6 * 66 * 16; idx += 512) {
        int seg = idx & 15;
        int pos = idx >> 4;
        int r   = pos / 66, col = pos % 66;
        int hh  = h0 + r - 1, ww = col - 1;
        float4 v = make_float4(0.f, 0.f, 0.f, 0.f);
        if (hh >= 0 && hh < HH && ww >= 0 && ww < WW)
            v = h4[(size_t)((((nb << 6) + hh) << 6) + ww) * 16 + seg];
        *(float4*)(slab + (r * 66 + col) * C2_SSTR + seg * 4) = v;
    }
    cp_wait<0>();
    __syncthreads();

    const int wid  = t >> 5;
    const int lane = t & 31;
    const int g    = lane >> 2;
    const int t4   = lane & 3;
    const int wm   = wid >> 1;
    const int wn   = wid & 1;
    const int p0   = wm << 5;
    const int r    = p0 >> 6;
    const int wcol = p0 & 63;

    float d[2][3][4] = {};

    #pragma unroll
    for (int kk = 0; kk < 9; kk++) {
        const int kh = kk / 3, kw = kk % 3;
        const float* arow = slab + ((r + kh) * 66 + kw + wcol + g) * C2_SSTR + (t4 << 1);
        const float* brow = ws + (wn * 24 + g) * C2_WSTR + kk * 64 + (t4 << 1);
        #pragma unroll
        for (int kt = 0; kt < 8; kt++) {
            const int k0 = kt << 3;
            uint32_t a[2][4], b[3][2];
            #pragma unroll
            for (int mi = 0; mi < 2; mi++) {
                const float* ap = arow + (mi << 4) * C2_SSTR + k0;
                float2 lo = *(const float2*)ap;
                float2 hi = *(const float2*)(ap + 8 * C2_SSTR);
                a[mi][0] = __float_as_uint(lo.x);
                a[mi][1] = __float_as_uint(hi.x);
                a[mi][2] = __float_as_uint(lo.y);
                a[mi][3] = __float_as_uint(hi.y);
            }
            #pragma unroll
            for (int ni = 0; ni < 3; ni++) {
                float2 bv = *(const float2*)(brow + (ni << 3) * C2_WSTR + k0);
                b[ni][0] = __float_as_uint(bv.x);
                b[ni][1] = __float_as_uint(bv.y);
            }
            #pragma unroll
            for (int mi = 0; mi < 2; mi++)
                #pragma unroll
                for (int ni = 0; ni < 3; ni++)
                    mma_tf32(d[mi][ni], a[mi], b[ni]);
        }
    }
    __syncthreads();

    float* bfs = ws;
    const float invs = rsqrtf(1.0f + 1e-3f);
    const float gs = gamma2[h0 + r] * invs;
    const float bb = beta2[h0 + r];
    #pragma unroll
    for (int mi = 0; mi < 2; mi++) {
        const int p = p0 + (mi << 4) + g;
        #pragma unroll
        for (int ni = 0; ni < 3; ni++) {
            const int c = wn * 24 + (ni << 3) + (t4 << 1);
            if (c < BSZ) {
                const float bj0 = b2[c], bj1 = b2[c + 1];
                bfs[p * 37 + c]           = fmaxf(fmaf(d[mi][ni][0] + bj0, gs, bb), 0.f);
                bfs[p * 37 + c + 1]       = fmaxf(fmaf(d[mi][ni][1] + bj1, gs, bb), 0.f);
                bfs[(p + 8) * 37 + c]     = fmaxf(fmaf(d[mi][ni][2] + bj0, gs, bb), 0.f);
                bfs[(p + 8) * 37 + c + 1] = fmaxf(fmaf(d[mi][ni][3] + bj1, gs, bb), 0.f);
            }
        }
    }
    __syncthreads();

    const int pp = t >> 1;
    const int half = t & 1;
    const float* bf = bfs + pp * 37;
    const int rr = pp >> 6, pw = pp & 63;
    float* outp = g_dyn + (size_t)((((nb << 6) + h0 + rr) << 6) + pw) * 54;
    #pragma unroll
    for (int q = 0; q < 27; q++) {
        int idx = half * 27 + q;
        int m = idx / 9, l = idx % 9;
        float s = 0.f;
        #pragma unroll
        for (int k = 0; k < 6; k++) s = fmaf(bf[m * 6 + k], bss[k * 9 + l], s);
        outp[idx] = s;
    }
}

// ===========================================================================
// Kernel 3a: bases_out A -> g_A[65536][768] (tf32, natural order)  (R11)
// ===========================================================================
#define K3A_SSTR 199
#define K3A_SMEM (CIN * K3A_SSTR * 4)

__global__ __launch_bounds__(256, 2)
void k3a_kernel(const float* __restrict__ x) {
    extern __shared__ float sm[];
    float* slab = sm;

    const int t  = threadIdx.x;
    const int bx = blockIdx.x;
    const int nb = bx >> 6;
    const int h  = bx & 63;

    const float4* x4 = (const float4*)x;
    for (int idx = t; idx < 3 * 66 * 32; idx += 256) {
        int ci4 = idx & 31;
        int col = (idx >> 5) % 66;
        int r   = idx / (32 * 66);
        int hh  = h + r - 1, ww = col - 1;
        float4 v = make_float4(0.f, 0.f, 0.f, 0.f);
        if (hh >= 0 && hh < HH && ww >= 0 && ww < WW)
            v = x4[((((nb << 6) + hh) << 6) + ww) * 32 + ci4];
        int so = r * 66 + col;
        slab[(ci4 * 4 + 0) * K3A_SSTR + so] = v.x;
        slab[(ci4 * 4 + 1) * K3A_SSTR + so] = v.y;
        slab[(ci4 * 4 + 2) * K3A_SSTR + so] = v.z;
        slab[(ci4 * 4 + 3) * K3A_SSTR + so] = v.w;
    }
    __syncthreads();

    const int w    = t >> 5;
    const int lane = t & 31;

    for (int pp = 0; pp < 8; pp++) {
        const int p = (w << 3) + pp;
        const size_t pix = (size_t)(bx << 6) + p;
        const float* dp = g_dyn + pix * 54;
        float dv[54];
        #pragma unroll
        for (int i = 0; i < 54; i++) dv[i] = __ldg(dp + i);

        float* arow = g_A + pix * 768;
        #pragma unroll
        for (int j = 0; j < 4; j++) {
            const int ch = lane + (j << 5);
            float pt[9];
            #pragma unroll
            for (int l = 0; l < 9; l++) {
                const int f  = ch * 9 + l;
                const int cc = f & 127;
                const int pi = f >> 7;
                pt[l] = slab[cc * K3A_SSTR + (pi / 3) * 66 + (pi % 3) + p];
            }
            uint32_t ov[6];
            #pragma unroll
            for (int m = 0; m < 6; m++) {
                float s = 0.f;
                #pragma unroll
                for (int l = 0; l < 9; l++) s = fmaf(dv[m * 9 + l], pt[l], s);
                ov[m] = tf32_rna(s);
            }
            float2* dst = (float2*)(arow + ch * 6);
            dst[0] = make_float2(__uint_as_float(ov[0]), __uint_as_float(ov[1]));
            dst[1] = make_float2(__uint_as_float(ov[2]), __uint_as_float(ov[3]));
            dst[2] = make_float2(__uint_as_float(ov[4]), __uint_as_float(ov[5]));
        }
    }
}

// ===========================================================================
// Kernel 3b: mma.sync tf32 GEMM out[65536,256] = A x B^T + bias
// grid = 512 (mt), block 512 (16 warps, 4m x 4n); block tile 128x256.
// R14: natural-pairing LDS.64 frag loads; stride 40 (conflict-free).
// ===========================================================================
#define K3B_STR  40
#define K3B_ACH  (128 * K3B_STR)
#define K3B_BCH  (256 * K3B_STR)
#define K3B_SMEM ((2 * K3B_ACH + 2 * K3B_BCH) * 4)   // 122880 B

__global__ __launch_bounds__(512, 1)
void k3b_kernel(const float* __restrict__ bias, float* __restrict__ out) {
    extern __shared__ float sm[];
    float* As[2] = { sm,              sm + K3B_ACH };
    float* Bs[2] = { sm + 2 * K3B_ACH, sm + 2 * K3B_ACH + K3B_BCH };

    const int t    = threadIdx.x;
    const int mt   = blockIdx.x;
    const int wid  = t >> 5;
    const int lane = t & 31;
    const int g    = lane >> 2;
    const int tid4 = lane & 3;

    const float* Abase = g_A + (size_t)(mt << 7) * 768;

    for (int i = t; i < 1024; i += 512) {
        int row = i >> 3, seg = i & 7;
        cp_async16(As[0] + row * K3B_STR + seg * 4, Abase + row * 768 + seg * 4);
    }
    for (int i = t; i < 2048; i += 512) {
        int row = i >> 3, seg = i & 7;
        cp_async16(Bs[0] + row * K3B_STR + seg * 4, g_Bt + row * 768 + seg * 4);
    }
    cp_commit();

    const int wm = wid >> 2, wn = wid & 3;
    const int m0 = wm << 5, n0 = wn << 6;
    float d[2][8][4] = {};

    for (int kc = 0; kc < 24; kc++) {
        cp_wait<0>();
        __syncthreads();
        if (kc < 23) {
            const int nc = kc + 1, buf = nc & 1;
            const float* as = Abase + nc * 32;
            const float* bs = g_Bt + nc * 32;
            for (int i = t; i < 1024; i += 512) {
                int row = i >> 3, seg = i & 7;
                cp_async16(As[buf] + row * K3B_STR + seg * 4, as + row * 768 + seg * 4);
            }
            for (int i = t; i < 2048; i += 512) {
                int row = i >> 3, seg = i & 7;
                cp_async16(Bs[buf] + row * K3B_STR + seg * 4, bs + row * 768 + seg * 4);
            }
            cp_commit();
        }
        const float* Ac = As[kc & 1];
        const float* Bc = Bs[kc & 1];

        #pragma unroll
        for (int kt = 0; kt < 4; kt++) {
            const int k0 = kt << 3;
            uint32_t a[2][4], b[8][2];
            #pragma unroll
            for (int mi = 0; mi < 2; mi++) {
                const float* ap = Ac + (m0 + (mi << 4) + g) * K3B_STR + k0 + (tid4 << 1);
                float2 lo = *(const float2*)ap;
                float2 hi = *(const float2*)(ap + 8 * K3B_STR);
                a[mi][0] = __float_as_uint(lo.x);
                a[mi][1] = __float_as_uint(hi.x);
                a[mi][2] = __float_as_uint(lo.y);
                a[mi][3] = __float_as_uint(hi.y);
            }
            #pragma unroll
            for (int ni = 0; ni < 8; ni++) {
                float2 bv = *(const float2*)(Bc + (n0 + (ni << 3) + g) * K3B_STR
                                             + k0 + (tid4 << 1));
                b[ni][0] = __float_as_uint(bv.x);
                b[ni][1] = __float_as_uint(bv.y);
            }
            #pragma unroll
            for (int mi = 0; mi < 2; mi++)
                #pragma unroll
                for (int ni = 0; ni < 8; ni++)
                    mma_tf32(d[mi][ni], a[mi], b[ni]);
        }
        __syncthreads();
    }

    const size_t rbase = (size_t)(mt << 7) + m0;
    const int    cbase = n0 + (tid4 << 1);
    #pragma unroll
    for (int mi = 0; mi < 2; mi++) {
        float* r0 = out + (rbase + (mi << 4) + g) * OO;
        float* r1 = r0 + 8 * OO;
        #pragma unroll
        for (int ni = 0; ni < 8; ni++) {
            const int c = cbase + (ni << 3);
            const float b0 = bias[c], b1 = bias[c + 1];
            *(float2*)(r0 + c) = make_float2(d[mi][ni][0] + b0, d[mi][ni][1] + b1);
            *(float2*)(r1 + c) = make_float2(d[mi][ni][2] + b0, d[mi][ni][3] + b1);
        }
    }
}

// ===========================================================================
extern "C" void kernel_launch(void* const* d_in, const int* in_sizes, int n_in,
                              void* d_out, int out_size) {
    const float* x      = (const float*)d_in[0];
    const float* w1     = (const float*)d_in[1];
    const float* b1     = (const float*)d_in[2];
    const float* gamma1 = (const float*)d_in[3];
    const float* beta1  = (const float*)d_in[4];
    const float* w2     = (const float*)d_in[5];
    const float* b2     = (const float*)d_in[6];
    const float* gamma2 = (const float*)d_in[7];
    const float* beta2  = (const float*)d_in[8];
    const float* bases  = (const float*)d_in[9];
    const float* coef   = (const float*)d_in[10];
    const float* bias   = (const float*)d_in[11];
    float* out = (float*)d_out;

    cudaFuncSetAttribute(conv1_kernel, cudaFuncAttributeMaxDynamicSharedMemorySize, C1_SMEM);
    cudaFuncSetAttribute(conv2_kernel, cudaFuncAttributeMaxDynamicSharedMemorySize, C2_SMEM);
    cudaFuncSetAttribute(k3a_kernel,   cudaFuncAttributeMaxDynamicSharedMemorySize, K3A_SMEM);
    cudaFuncSetAttribute(k3b_kernel,   cudaFuncAttributeMaxDynamicSharedMemorySize, K3B_SMEM);

    prepW_kernel <<<576, 128>>>(w1);
    prepW2_kernel<<<48,  576>>>(w2);
    prepB_kernel <<<OO,  256>>>(coef);
    conv1_kernel<<<NB * HH / 2, 256, C1_SMEM>>>(x, b1, gamma1, beta1);
    conv2_kernel<<<NB * HH / 4, 512, C2_SMEM>>>(b2, gamma2, beta2, bases);
    k3a_kernel  <<<NB * HH,     256, K3A_SMEM>>>(x);
    k3b_kernel  <<<512,         512, K3B_SMEM>>>(bias, out);
}

// round 15
// speedup vs baseline: 1.1213x; 1.0004x over previous
#include <cuda_runtime.h>
#include <cuda_bf16.h>
#include <cstdint>

// ---------------------------------------------------------------------------
// Conv_DCFD on sm_100 (no tcgen05 in this toolchain): conv1, conv2 and the
// final 1x1 GEMM all run on the tensor pipe via mma.sync tf32 (rna-rounded).
// R15: conv1 de-perm8'd -- natural-pairing LDS.64 frag loads (same consumer
// code), natural g_W1t, STS.128 slab fill (producer scatter removed).
// Shapes: N=16,H=64,W=64,C=128, inter=64, bases=36, M=6, O=256
// ---------------------------------------------------------------------------

#define NB   16
#define HH   64
#define WW   64
#define CIN  128
#define CMID 64
#define BSZ  36
#define OO   256

// scratch (no cudaMalloc allowed)
__device__ float g_h   [NB * HH * WW * CMID];     // 16.8 MB
__device__ float g_dyn [NB * HH * WW * 54];       // 14.2 MB
__device__ float g_A   [NB * HH * WW * 768];      // 201 MB (tf32, natural order)
__device__ float g_Bt  [OO * 768];                // 768 KB (B^T, tf32, natural)
__device__ float g_W1t [9 * CMID * CIN];          // w1^T per tap (natural)
__device__ float g_W2t [48 * 576];                // w2^T co-major (natural)

__device__ __forceinline__ void cp_async16(void* smem_dst, const void* gmem_src) {
    unsigned s = (unsigned)__cvta_generic_to_shared(smem_dst);
    asm volatile("cp.async.cg.shared.global [%0], [%1], 16;\n" :: "r"(s), "l"(gmem_src));
}
__device__ __forceinline__ void cp_commit() { asm volatile("cp.async.commit_group;\n"); }
template<int N> __device__ __forceinline__ void cp_wait() {
    asm volatile("cp.async.wait_group %0;\n" :: "n"(N));
}
__device__ __forceinline__ uint32_t tf32_rna(float v) {
    uint32_t r;
    asm("cvt.rna.tf32.f32 %0, %1;" : "=r"(r) : "f"(v));
    return r;
}
__device__ __forceinline__ void mma_tf32(float* d, const uint32_t* a, const uint32_t* b) {
    asm volatile(
        "mma.sync.aligned.m16n8k8.row.col.f32.tf32.tf32.f32 "
        "{%0,%1,%2,%3}, {%4,%5,%6,%7}, {%8,%9}, {%0,%1,%2,%3};"
        : "+f"(d[0]), "+f"(d[1]), "+f"(d[2]), "+f"(d[3])
        : "r"(a[0]), "r"(a[1]), "r"(a[2]), "r"(a[3]), "r"(b[0]), "r"(b[1]));
}

// ===========================================================================
// prep kernels (all natural order now)
// ===========================================================================
__global__ void prepW_kernel(const float* __restrict__ w1) {
    const int bx = blockIdx.x;          // kk*64+co (576)
    const int t  = threadIdx.x;         // ci (128)
    const int kk = bx >> 6, co = bx & 63;
    g_W1t[bx * 128 + t] = __uint_as_float(tf32_rna(w1[(kk * 128 + t) * 64 + co]));
}

__global__ void prepW2_kernel(const float* __restrict__ w2) {
    const int n = blockIdx.x;           // 0..47 (co, padded)
    const int k = threadIdx.x;          // 0..575 (kk*64+ci)
    float v = 0.f;
    if (n < BSZ) {
        const int kk = k >> 6, ci = k & 63;
        v = w2[(kk * 64 + ci) * BSZ + n];
    }
    g_W2t[n * 576 + k] = __uint_as_float(tf32_rna(v));
}

__global__ void prepB_kernel(const float* __restrict__ coef) {
    const int n = blockIdx.x;
    const int t = threadIdx.x;
    #pragma unroll
    for (int q = 0; q < 3; q++) {
        int k = q * 256 + t;
        g_Bt[n * 768 + k] = __uint_as_float(tf32_rna(coef[k * OO + n]));
    }
}

// ===========================================================================
// Kernel 1: conv1 via mma.sync tf32 + BN(axis=H) + ReLU -> g_h
// grid = 512 (2 rows), block 256 (8 warps, 4m x 2n), warp 32px x 32co.
// Natural layouts, strides 136; natural-pairing LDS.64 frag loads
// (thread t4 takes k-pair (2t4, 2t4+1) in both A and B -> exact GEMM).
// Slab fill is STS.128 (no scatter).
// ===========================================================================
#define C1_SSTR  136
#define C1_SLAB  (264 * C1_SSTR)        // 35904 floats
#define C1_WSTR  136
#define C1_WCH   (CMID * C1_WSTR)       // 8704 floats
#define C1_SMEM  ((C1_SLAB + 2 * C1_WCH) * 4)   // 213248 B

__global__ __launch_bounds__(256, 1)
void conv1_kernel(const float* __restrict__ x, const float* __restrict__ b1,
                  const float* __restrict__ gamma1, const float* __restrict__ beta1) {
    extern __shared__ float sm[];
    float* slab = sm;
    float* wbuf = sm + C1_SLAB;

    const int t  = threadIdx.x;
    const int bx = blockIdx.x;
    const int nb = bx >> 5;
    const int h0 = (bx & 31) << 1;

    for (int i = t; i < 2048; i += 256) {
        int row = i >> 5, seg = i & 31;
        cp_async16(wbuf + row * C1_WSTR + seg * 4, g_W1t + row * 128 + seg * 4);
    }
    cp_commit();

    // slab: rows h0-1..h0+2 (4), cols -1..64 (66), 128 ci, tf32 rounded, STS.128
    const float4* x4 = (const float4*)x;
    for (int idx = t; idx < 4 * 66 * 32; idx += 256) {
        int ci4 = idx & 31;
        int col = (idx >> 5) % 66;
        int r   = idx / (32 * 66);
        int hh  = h0 + r - 1, ww = col - 1;
        float4 v = make_float4(0.f, 0.f, 0.f, 0.f);
        if (hh >= 0 && hh < HH && ww >= 0 && ww < WW)
            v = x4[((((nb << 6) + hh) << 6) + ww) * 32 + ci4];
        float4 o;
        o.x = __uint_as_float(tf32_rna(v.x));
        o.y = __uint_as_float(tf32_rna(v.y));
        o.z = __uint_as_float(tf32_rna(v.z));
        o.w = __uint_as_float(tf32_rna(v.w));
        *(float4*)(slab + (r * 66 + col) * C1_SSTR + ci4 * 4) = o;
    }
    cp_wait<0>();
    __syncthreads();

    const int wid  = t >> 5;
    const int lane = t & 31;
    const int g    = lane >> 2;
    const int t4   = lane & 3;
    const int wm   = wid >> 1;
    const int wn   = wid & 1;
    const int p0   = wm << 5;
    const int r    = p0 >> 6;
    const int col0 = p0 & 63;

    float d[2][4][4] = {};

    for (int kk = 0; kk < 9; kk++) {
        const float* wb = wbuf + (kk & 1) * C1_WCH;
        if (kk < 8) {
            float* dst = wbuf + ((kk + 1) & 1) * C1_WCH;
            const float* src = g_W1t + (kk + 1) * 8192;
            for (int i = t; i < 2048; i += 256) {
                int row = i >> 5, seg = i & 31;
                cp_async16(dst + row * C1_WSTR + seg * 4, src + row * 128 + seg * 4);
            }
            cp_commit();
        }
        const int kh = kk / 3, kw = kk % 3;
        const float* arow = slab + ((r + kh) * 66 + kw + col0 + g) * C1_SSTR + (t4 << 1);

        #pragma unroll
        for (int kt = 0; kt < 16; kt++) {
            const int k0 = kt << 3;
            uint32_t a[2][4], b[4][2];
            #pragma unroll
            for (int mi = 0; mi < 2; mi++) {
                const float* ap = arow + (mi << 4) * C1_SSTR + k0;
                float2 lo = *(const float2*)ap;
                float2 hi = *(const float2*)(ap + 8 * C1_SSTR);
                a[mi][0] = __float_as_uint(lo.x);
                a[mi][1] = __float_as_uint(hi.x);
                a[mi][2] = __float_as_uint(lo.y);
                a[mi][3] = __float_as_uint(hi.y);
            }
            #pragma unroll
            for (int ni = 0; ni < 4; ni++) {
                float2 bv = *(const float2*)(wb + ((wn << 5) + (ni << 3) + g) * C1_WSTR
                                             + k0 + (t4 << 1));
                b[ni][0] = __float_as_uint(bv.x);
                b[ni][1] = __float_as_uint(bv.y);
            }
            #pragma unroll
            for (int mi = 0; mi < 2; mi++)
                #pragma unroll
                for (int ni = 0; ni < 4; ni++)
                    mma_tf32(d[mi][ni], a[mi], b[ni]);
        }
        cp_wait<0>();
        __syncthreads();
    }

    const float invs = rsqrtf(1.0f + 1e-3f);
    const float gs = gamma1[h0 + r] * invs;
    const float bb = beta1[h0 + r];
    #pragma unroll
    for (int mi = 0; mi < 2; mi++) {
        const int p = p0 + (mi << 4) + g;
        float* r0 = g_h + ((size_t)(bx << 7) + p) * CMID;
        float* r1 = r0 + 8 * CMID;
        #pragma unroll
        for (int ni = 0; ni < 4; ni++) {
            const int c = (wn << 5) + (ni << 3) + (t4 << 1);
            const float bc0 = b1[c], bc1 = b1[c + 1];
            float2 v0, v1;
            v0.x = fmaxf(fmaf(d[mi][ni][0] + bc0, gs, bb), 0.f);
            v0.y = fmaxf(fmaf(d[mi][ni][1] + bc1, gs, bb), 0.f);
            v1.x = fmaxf(fmaf(d[mi][ni][2] + bc0, gs, bb), 0.f);
            v1.y = fmaxf(fmaf(d[mi][ni][3] + bc1, gs, bb), 0.f);
            *(float2*)(r0 + c) = v0;
            *(float2*)(r1 + c) = v1;
        }
    }
}

// ===========================================================================
// Kernel 2: conv2 via mma.sync tf32 + BN + ReLU + xFB -> g_dyn  (R14)
// grid = 256 (4 rows), block 512 (16 warps, 8m x 2n), warp 32px x 24co.
// Natural-pairing LDS.64 frag loads; strides 72/584.
// ===========================================================================
#define C2_SSTR  72
#define C2_SLAB  (396 * C2_SSTR)        // 28512 floats
#define C2_WSTR  584
#define C2_WS    (48 * C2_WSTR)         // 28032 floats
#define C2_SMEM  ((C2_SLAB + C2_WS + 64) * 4)   // 226432 B

__global__ __launch_bounds__(512, 1)
void conv2_kernel(const float* __restrict__ b2, const float* __restrict__ gamma2,
                  const float* __restrict__ beta2, const float* __restrict__ bases) {
    extern __shared__ float sm[];
    float* slab = sm;
    float* ws   = sm + C2_SLAB;
    float* bss  = sm + C2_SLAB + C2_WS;

    const int t  = threadIdx.x;
    const int bx = blockIdx.x;
    const int nb = bx >> 4;
    const int h0 = (bx & 15) << 2;

    for (int i = t; i < 6912; i += 512) {
        int row = i / 144, seg = i % 144;
        cp_async16(ws + row * C2_WSTR + seg * 4, g_W2t + row * 576 + seg * 4);
    }
    cp_commit();
    if (t < 54) bss[t] = bases[t];

    const float4* h4 = (const float4*)g_h;
    for (int idx = t; idx < 6 * 66 * 16; idx += 512) {
        int seg = idx & 15;
        int pos = idx >> 4;
        int r   = pos / 66, col = pos % 66;
        int hh  = h0 + r - 1, ww = col - 1;
        float4 v = make_float4(0.f, 0.f, 0.f, 0.f);
        if (hh >= 0 && hh < HH && ww >= 0 && ww < WW)
            v = h4[(size_t)((((nb << 6) + hh) << 6) + ww) * 16 + seg];
        *(float4*)(slab + (r * 66 + col) * C2_SSTR + seg * 4) = v;
    }
    cp_wait<0>();
    __syncthreads();

    const int wid  = t >> 5;
    const int lane = t & 31;
    const int g    = lane >> 2;
    const int t4   = lane & 3;
    const int wm   = wid >> 1;
    const int wn   = wid & 1;
    const int p0   = wm << 5;
    const int r    = p0 >> 6;
    const int wcol = p0 & 63;

    float d[2][3][4] = {};

    #pragma unroll
    for (int kk = 0; kk < 9; kk++) {
        const int kh = kk / 3, kw = kk % 3;
        const float* arow = slab + ((r + kh) * 66 + kw + wcol + g) * C2_SSTR + (t4 << 1);
        const float* brow = ws + (wn * 24 + g) * C2_WSTR + kk * 64 + (t4 << 1);
        #pragma unroll
        for (int kt = 0; kt < 8; kt++) {
            const int k0 = kt << 3;
            uint32_t a[2][4], b[3][2];
            #pragma unroll
            for (int mi = 0; mi < 2; mi++) {
                const float* ap = arow + (mi << 4) * C2_SSTR + k0;
                float2 lo = *(const float2*)ap;
                float2 hi = *(const float2*)(ap + 8 * C2_SSTR);
                a[mi][0] = __float_as_uint(lo.x);
                a[mi][1] = __float_as_uint(hi.x);
                a[mi][2] = __float_as_uint(lo.y);
                a[mi][3] = __float_as_uint(hi.y);
            }
            #pragma unroll
            for (int ni = 0; ni < 3; ni++) {
                float2 bv = *(const float2*)(brow + (ni << 3) * C2_WSTR + k0);
                b[ni][0] = __float_as_uint(bv.x);
                b[ni][1] = __float_as_uint(bv.y);
            }
            #pragma unroll
            for (int mi = 0; mi < 2; mi++)
                #pragma unroll
                for (int ni = 0; ni < 3; ni++)
                    mma_tf32(d[mi][ni], a[mi], b[ni]);
        }
    }
    __syncthreads();

    float* bfs = ws;
    const float invs = rsqrtf(1.0f + 1e-3f);
    const float gs = gamma2[h0 + r] * invs;
    const float bb = beta2[h0 + r];
    #pragma unroll
    for (int mi = 0; mi < 2; mi++) {
        const int p = p0 + (mi << 4) + g;
        #pragma unroll
        for (int ni = 0; ni < 3; ni++) {
            const int c = wn * 24 + (ni << 3) + (t4 << 1);
            if (c < BSZ) {
                const float bj0 = b2[c], bj1 = b2[c + 1];
                bfs[p * 37 + c]           = fmaxf(fmaf(d[mi][ni][0] + bj0, gs, bb), 0.f);
                bfs[p * 37 + c + 1]       = fmaxf(fmaf(d[mi][ni][1] + bj1, gs, bb), 0.f);
                bfs[(p + 8) * 37 + c]     = fmaxf(fmaf(d[mi][ni][2] + bj0, gs, bb), 0.f);
                bfs[(p + 8) * 37 + c + 1] = fmaxf(fmaf(d[mi][ni][3] + bj1, gs, bb), 0.f);
            }
        }
    }
    __syncthreads();

    const int pp = t >> 1;
    const int half = t & 1;
    const float* bf = bfs + pp * 37;
    const int rr = pp >> 6, pw = pp & 63;
    float* outp = g_dyn + (size_t)((((nb << 6) + h0 + rr) << 6) + pw) * 54;
    #pragma unroll
    for (int q = 0; q < 27; q++) {
        int idx = half * 27 + q;
        int m = idx / 9, l = idx % 9;
        float s = 0.f;
        #pragma unroll
        for (int k = 0; k < 6; k++) s = fmaf(bf[m * 6 + k], bss[k * 9 + l], s);
        outp[idx] = s;
    }
}

// ===========================================================================
// Kernel 3a: bases_out A -> g_A[65536][768] (tf32, natural order)  (R11)
// ===========================================================================
#define K3A_SSTR 199
#define K3A_SMEM (CIN * K3A_SSTR * 4)

__global__ __launch_bounds__(256, 2)
void k3a_kernel(const float* __restrict__ x) {
    extern __shared__ float sm[];
    float* slab = sm;

    const int t  = threadIdx.x;
    const int bx = blockIdx.x;
    const int nb = bx >> 6;
    const int h  = bx & 63;

    const float4* x4 = (const float4*)x;
    for (int idx = t; idx < 3 * 66 * 32; idx += 256) {
        int ci4 = idx & 31;
        int col = (idx >> 5) % 66;
        int r   = idx / (32 * 66);
        int hh  = h + r - 1, ww = col - 1;
        float4 v = make_float4(0.f, 0.f, 0.f, 0.f);
        if (hh >= 0 && hh < HH && ww >= 0 && ww < WW)
            v = x4[((((nb << 6) + hh) << 6) + ww) * 32 + ci4];
        int so = r * 66 + col;
        slab[(ci4 * 4 + 0) * K3A_SSTR + so] = v.x;
        slab[(ci4 * 4 + 1) * K3A_SSTR + so] = v.y;
        slab[(ci4 * 4 + 2) * K3A_SSTR + so] = v.z;
        slab[(ci4 * 4 + 3) * K3A_SSTR + so] = v.w;
    }
    __syncthreads();

    const int w    = t >> 5;
    const int lane = t & 31;

    for (int pp = 0; pp < 8; pp++) {
        const int p = (w << 3) + pp;
        const size_t pix = (size_t)(bx << 6) + p;
        const float* dp = g_dyn + pix * 54;
        float dv[54];
        #pragma unroll
        for (int i = 0; i < 54; i++) dv[i] = __ldg(dp + i);

        float* arow = g_A + pix * 768;
        #pragma unroll
        for (int j = 0; j < 4; j++) {
            const int ch = lane + (j << 5);
            float pt[9];
            #pragma unroll
            for (int l = 0; l < 9; l++) {
                const int f  = ch * 9 + l;
                const int cc = f & 127;
                const int pi = f >> 7;
                pt[l] = slab[cc * K3A_SSTR + (pi / 3) * 66 + (pi % 3) + p];
            }
            uint32_t ov[6];
            #pragma unroll
            for (int m = 0; m < 6; m++) {
                float s = 0.f;
                #pragma unroll
                for (int l = 0; l < 9; l++) s = fmaf(dv[m * 9 + l], pt[l], s);
                ov[m] = tf32_rna(s);
            }
            float2* dst = (float2*)(arow + ch * 6);
            dst[0] = make_float2(__uint_as_float(ov[0]), __uint_as_float(ov[1]));
            dst[1] = make_float2(__uint_as_float(ov[2]), __uint_as_float(ov[3]));
            dst[2] = make_float2(__uint_as_float(ov[4]), __uint_as_float(ov[5]));
        }
    }
}

// ===========================================================================
// Kernel 3b: mma.sync tf32 GEMM out[65536,256] = A x B^T + bias  (R14)
// grid = 512 (mt), block 512 (16 warps, 4m x 4n); block tile 128x256.
// Natural-pairing LDS.64 frag loads; stride 40.
// ===========================================================================
#define K3B_STR  40
#define K3B_ACH  (128 * K3B_STR)
#define K3B_BCH  (256 * K3B_STR)
#define K3B_SMEM ((2 * K3B_ACH + 2 * K3B_BCH) * 4)   // 122880 B

__global__ __launch_bounds__(512, 1)
void k3b_kernel(const float* __restrict__ bias, float* __restrict__ out) {
    extern __shared__ float sm[];
    float* As[2] = { sm,              sm + K3B_ACH };
    float* Bs[2] = { sm + 2 * K3B_ACH, sm + 2 * K3B_ACH + K3B_BCH };

    const int t    = threadIdx.x;
    const int mt   = blockIdx.x;
    const int wid  = t >> 5;
    const int lane = t & 31;
    const int g    = lane >> 2;
    const int tid4 = lane & 3;

    const float* Abase = g_A + (size_t)(mt << 7) * 768;

    for (int i = t; i < 1024; i += 512) {
        int row = i >> 3, seg = i & 7;
        cp_async16(As[0] + row * K3B_STR + seg * 4, Abase + row * 768 + seg * 4);
    }
    for (int i = t; i < 2048; i += 512) {
        int row = i >> 3, seg = i & 7;
        cp_async16(Bs[0] + row * K3B_STR + seg * 4, g_Bt + row * 768 + seg * 4);
    }
    cp_commit();

    const int wm = wid >> 2, wn = wid & 3;
    const int m0 = wm << 5, n0 = wn << 6;
    float d[2][8][4] = {};

    for (int kc = 0; kc < 24; kc++) {
        cp_wait<0>();
        __syncthreads();
        if (kc < 23) {
            const int nc = kc + 1, buf = nc & 1;
            const float* as = Abase + nc * 32;
            const float* bs = g_Bt + nc * 32;
            for (int i = t; i < 1024; i += 512) {
                int row = i >> 3, seg = i & 7;
                cp_async16(As[buf] + row * K3B_STR + seg * 4, as + row * 768 + seg * 4);
            }
            for (int i = t; i < 2048; i += 512) {
                int row = i >> 3, seg = i & 7;
                cp_async16(Bs[buf] + row * K3B_STR + seg * 4, bs + row * 768 + seg * 4);
            }
            cp_commit();
        }
        const float* Ac = As[kc & 1];
        const float* Bc = Bs[kc & 1];

        #pragma unroll
        for (int kt = 0; kt < 4; kt++) {
            const int k0 = kt << 3;
            uint32_t a[2][4], b[8][2];
            #pragma unroll
            for (int mi = 0; mi < 2; mi++) {
                const float* ap = Ac + (m0 + (mi << 4) + g) * K3B_STR + k0 + (tid4 << 1);
                float2 lo = *(const float2*)ap;
                float2 hi = *(const float2*)(ap + 8 * K3B_STR);
                a[mi][0] = __float_as_uint(lo.x);
                a[mi][1] = __float_as_uint(hi.x);
                a[mi][2] = __float_as_uint(lo.y);
                a[mi][3] = __float_as_uint(hi.y);
            }
            #pragma unroll
            for (int ni = 0; ni < 8; ni++) {
                float2 bv = *(const float2*)(Bc + (n0 + (ni << 3) + g) * K3B_STR
                                             + k0 + (tid4 << 1));
                b[ni][0] = __float_as_uint(bv.x);
                b[ni][1] = __float_as_uint(bv.y);
            }
            #pragma unroll
            for (int mi = 0; mi < 2; mi++)
                #pragma unroll
                for (int ni = 0; ni < 8; ni++)
                    mma_tf32(d[mi][ni], a[mi], b[ni]);
        }
        __syncthreads();
    }

    const size_t rbase = (size_t)(mt << 7) + m0;
    const int    cbase = n0 + (tid4 << 1);
    #pragma unroll
    for (int mi = 0; mi < 2; mi++) {
        float* r0 = out + (rbase + (mi << 4) + g) * OO;
        float* r1 = r0 + 8 * OO;
        #pragma unroll
        for (int ni = 0; ni < 8; ni++) {
            const int c = cbase + (ni << 3);
            const float b0 = bias[c], b1 = bias[c + 1];
            *(float2*)(r0 + c) = make_float2(d[mi][ni][0] + b0, d[mi][ni][1] + b1);
            *(float2*)(r1 + c) = make_float2(d[mi][ni][2] + b0, d[mi][ni][3] + b1);
        }
    }
}

// ===========================================================================
extern "C" void kernel_launch(void* const* d_in, const int* in_sizes, int n_in,
                              void* d_out, int out_size) {
    const float* x      = (const float*)d_in[0];
    const float* w1     = (const float*)d_in[1];
    const float* b1     = (const float*)d_in[2];
    const float* gamma1 = (const float*)d_in[3];
    const float* beta1  = (const float*)d_in[4];
    const float* w2     = (const float*)d_in[5];
    const float* b2     = (const float*)d_in[6];
    const float* gamma2 = (const float*)d_in[7];
    const float* beta2  = (const float*)d_in[8];
    const float* bases  = (const float*)d_in[9];
    const float* coef   = (const float*)d_in[10];
    const float* bias   = (const float*)d_in[11];
    float* out = (float*)d_out;

    cudaFuncSetAttribute(conv1_kernel, cudaFuncAttributeMaxDynamicSharedMemorySize, C1_SMEM);
    cudaFuncSetAttribute(conv2_kernel, cudaFuncAttributeMaxDynamicSharedMemorySize, C2_SMEM);
    cudaFuncSetAttribute(k3a_kernel,   cudaFuncAttributeMaxDynamicSharedMemorySize, K3A_SMEM);
    cudaFuncSetAttribute(k3b_kernel,   cudaFuncAttributeMaxDynamicSharedMemorySize, K3B_SMEM);

    prepW_kernel <<<576, 128>>>(w1);
    prepW2_kernel<<<48,  576>>>(w2);
    prepB_kernel <<<OO,  256>>>(coef);
    conv1_kernel<<<NB * HH / 2, 256, C1_SMEM>>>(x, b1, gamma1, beta1);
    conv2_kernel<<<NB * HH / 4, 512, C2_SMEM>>>(b2, gamma2, beta2, bases);
    k3a_kernel  <<<NB * HH,     256, K3A_SMEM>>>(x);
    k3b_kernel  <<<512,         512, K3B_SMEM>>>(bias, out);
}

// round 16
// speedup vs baseline: 1.1263x; 1.0045x over previous
#include <cuda_runtime.h>
#include <cuda_bf16.h>
#include <cstdint>

// ---------------------------------------------------------------------------
// Conv_DCFD on sm_100 (no tcgen05 in this toolchain): conv1, conv2 and the
// final 1x1 GEMM all run on the tensor pipe via mma.sync tf32 (rna-rounded).
// R16: conv1 retiled to conv2's proven 512-thread/16-warp skeleton (4-row
// block, ci-half-split slab); k3b gets a 3-stage cp.async pipeline.
// Shapes: N=16,H=64,W=64,C=128, inter=64, bases=36, M=6, O=256
// ---------------------------------------------------------------------------

#define NB   16
#define HH   64
#define WW   64
#define CIN  128
#define CMID 64
#define BSZ  36
#define OO   256

// scratch (no cudaMalloc allowed)
__device__ float g_h   [NB * HH * WW * CMID];     // 16.8 MB
__device__ float g_dyn [NB * HH * WW * 54];       // 14.2 MB
__device__ float g_A   [NB * HH * WW * 768];      // 201 MB (tf32, natural order)
__device__ float g_Bt  [OO * 768];                // 768 KB (B^T, tf32, natural)
__device__ float g_W1t [9 * CMID * CIN];          // w1^T per tap (natural)
__device__ float g_W2t [48 * 576];                // w2^T co-major (natural)

__device__ __forceinline__ void cp_async16(void* smem_dst, const void* gmem_src) {
    unsigned s = (unsigned)__cvta_generic_to_shared(smem_dst);
    asm volatile("cp.async.cg.shared.global [%0], [%1], 16;\n" :: "r"(s), "l"(gmem_src));
}
__device__ __forceinline__ void cp_commit() { asm volatile("cp.async.commit_group;\n"); }
template<int N> __device__ __forceinline__ void cp_wait() {
    asm volatile("cp.async.wait_group %0;\n" :: "n"(N));
}
__device__ __forceinline__ uint32_t tf32_rna(float v) {
    uint32_t r;
    asm("cvt.rna.tf32.f32 %0, %1;" : "=r"(r) : "f"(v));
    return r;
}
__device__ __forceinline__ void mma_tf32(float* d, const uint32_t* a, const uint32_t* b) {
    asm volatile(
        "mma.sync.aligned.m16n8k8.row.col.f32.tf32.tf32.f32 "
        "{%0,%1,%2,%3}, {%4,%5,%6,%7}, {%8,%9}, {%0,%1,%2,%3};"
        : "+f"(d[0]), "+f"(d[1]), "+f"(d[2]), "+f"(d[3])
        : "r"(a[0]), "r"(a[1]), "r"(a[2]), "r"(a[3]), "r"(b[0]), "r"(b[1]));
}

// ===========================================================================
// prep kernels (all natural order)
// ===========================================================================
__global__ void prepW_kernel(const float* __restrict__ w1) {
    const int bx = blockIdx.x;          // kk*64+co (576)
    const int t  = threadIdx.x;         // ci (128)
    const int kk = bx >> 6, co = bx & 63;
    g_W1t[bx * 128 + t] = __uint_as_float(tf32_rna(w1[(kk * 128 + t) * 64 + co]));
}

__global__ void prepW2_kernel(const float* __restrict__ w2) {
    const int n = blockIdx.x;           // 0..47 (co, padded)
    const int k = threadIdx.x;          // 0..575 (kk*64+ci)
    float v = 0.f;
    if (n < BSZ) {
        const int kk = k >> 6, ci = k & 63;
        v = w2[(kk * 64 + ci) * BSZ + n];
    }
    g_W2t[n * 576 + k] = __uint_as_float(tf32_rna(v));
}

__global__ void prepB_kernel(const float* __restrict__ coef) {
    const int n = blockIdx.x;
    const int t = threadIdx.x;
    #pragma unroll
    for (int q = 0; q < 3; q++) {
        int k = q * 256 + t;
        g_Bt[n * 768 + k] = __uint_as_float(tf32_rna(coef[k * OO + n]));
    }
}

// ===========================================================================
// Kernel 1: conv1 via mma.sync tf32 + BN(axis=H) + ReLU -> g_h
// R16: grid = 256 (nb, h0 = 4 rows = 256 px), block 512 (16 warps, 8m x 2n),
// warp tile 32px x 32co. K=1152 split as 2 ci-halves x 9 taps x 64.
// slab: 64 ci of rows h0-1..h0+4 (6x66), stride 72; reloaded at half switch.
// wbuf: [64co][64ci] stride 72, double-buffered per tap-half from g_W1t.
// Natural-pairing LDS.64 frag loads throughout (conv2's verified layout).
// ===========================================================================
#define C1_SSTR  72
#define C1_SLAB  (396 * C1_SSTR)        // 28512 floats = 114048 B
#define C1_WSTR  72
#define C1_WCH   (CMID * C1_WSTR)       // 4608 floats
#define C1_SMEM  ((C1_SLAB + 2 * C1_WCH) * 4)   // 150912 B

__global__ __launch_bounds__(512, 1)
void conv1_kernel(const float* __restrict__ x, const float* __restrict__ b1,
                  const float* __restrict__ gamma1, const float* __restrict__ beta1) {
    extern __shared__ float sm[];
    float* slab = sm;
    float* wbuf = sm + C1_SLAB;

    const int t  = threadIdx.x;
    const int bx = blockIdx.x;
    const int nb = bx >> 4;
    const int h0 = (bx & 15) << 2;

    // prefetch weights for step 0 (tap 0, half 0): 64 co rows x 16 float4 segs
    for (int i = t; i < 1024; i += 512) {
        int row = i >> 4, seg = i & 15;
        cp_async16(wbuf + row * C1_WSTR + seg * 4, g_W1t + row * 128 + seg * 4);
    }
    cp_commit();

    // slab fill, half 0: rows h0-1..h0+4 (6), cols -1..64 (66), ci 0..63
    const float4* x4 = (const float4*)x;
    for (int idx = t; idx < 6 * 66 * 16; idx += 512) {
        int seg = idx & 15;
        int pos = idx >> 4;
        int rr = pos / 66, col = pos % 66;
        int hh = h0 + rr - 1, ww = col - 1;
        float4 v = make_float4(0.f, 0.f, 0.f, 0.f);
        if (hh >= 0 && hh < HH && ww >= 0 && ww < WW)
            v = x4[((((nb << 6) + hh) << 6) + ww) * 32 + seg];
        float4 o;
        o.x = __uint_as_float(tf32_rna(v.x));
        o.y = __uint_as_float(tf32_rna(v.y));
        o.z = __uint_as_float(tf32_rna(v.z));
        o.w = __uint_as_float(tf32_rna(v.w));
        *(float4*)(slab + (rr * 66 + col) * C1_SSTR + seg * 4) = o;
    }
    cp_wait<0>();
    __syncthreads();

    const int wid  = t >> 5;
    const int lane = t & 31;
    const int g    = lane >> 2;
    const int t4   = lane & 3;
    const int wm   = wid >> 1;           // 0..7 (32-px group)
    const int wn   = wid & 1;            // 0..1 (32-co group)
    const int p0   = wm << 5;            // pixel base 0..224
    const int r    = p0 >> 6;            // image row within quad
    const int wcol = p0 & 63;

    float d[2][4][4] = {};

    for (int step = 0; step < 18; step++) {
        const int kk = step % 9;
        const float* wb = wbuf + (step & 1) * C1_WCH;

        if (step < 17) {
            const int ns = step + 1;
            const int nk = ns % 9, nh = ns / 9;
            float* dst = wbuf + (ns & 1) * C1_WCH;
            const float* src = g_W1t + nk * 8192 + nh * 64;
            for (int i = t; i < 1024; i += 512) {
                int row = i >> 4, seg = i & 15;
                cp_async16(dst + row * C1_WSTR + seg * 4, src + row * 128 + seg * 4);
            }
            cp_commit();
        }

        const int kh = kk / 3, kw = kk % 3;
        const float* arow = slab + ((r + kh) * 66 + kw + wcol + g) * C1_SSTR + (t4 << 1);

        #pragma unroll
        for (int kt = 0; kt < 8; kt++) {
            const int k0 = kt << 3;
            uint32_t a[2][4], b[4][2];
            #pragma unroll
            for (int mi = 0; mi < 2; mi++) {
                const float* ap = arow + (mi << 4) * C1_SSTR + k0;
                float2 lo = *(const float2*)ap;
                float2 hi = *(const float2*)(ap + 8 * C1_SSTR);
                a[mi][0] = __float_as_uint(lo.x);
                a[mi][1] = __float_as_uint(hi.x);
                a[mi][2] = __float_as_uint(lo.y);
                a[mi][3] = __float_as_uint(hi.y);
            }
            #pragma unroll
            for (int ni = 0; ni < 4; ni++) {
                float2 bv = *(const float2*)(wb + ((wn << 5) + (ni << 3) + g) * C1_WSTR
                                             + k0 + (t4 << 1));
                b[ni][0] = __float_as_uint(bv.x);
                b[ni][1] = __float_as_uint(bv.y);
            }
            #pragma unroll
            for (int mi = 0; mi < 2; mi++)
                #pragma unroll
                for (int ni = 0; ni < 4; ni++)
                    mma_tf32(d[mi][ni], a[mi], b[ni]);
        }
        cp_wait<0>();
        __syncthreads();

        if (step == 8) {
            // reload slab with ci half 1 (all compute on half 0 is done)
            for (int idx = t; idx < 6 * 66 * 16; idx += 512) {
                int seg = idx & 15;
                int pos = idx >> 4;
                int rr = pos / 66, col = pos % 66;
                int hh = h0 + rr - 1, ww = col - 1;
                float4 v = make_float4(0.f, 0.f, 0.f, 0.f);
                if (hh >= 0 && hh < HH && ww >= 0 && ww < WW)
                    v = x4[((((nb << 6) + hh) << 6) + ww) * 32 + 16 + seg];
                float4 o;
                o.x = __uint_as_float(tf32_rna(v.x));
                o.y = __uint_as_float(tf32_rna(v.y));
                o.z = __uint_as_float(tf32_rna(v.z));
                o.w = __uint_as_float(tf32_rna(v.w));
                *(float4*)(slab + (rr * 66 + col) * C1_SSTR + seg * 4) = o;
            }
            __syncthreads();
        }
    }

    // epilogue: BN(axis=H) + ReLU + bias
    const float invs = rsqrtf(1.0f + 1e-3f);
    const float gs = gamma1[h0 + r] * invs;
    const float bb = beta1[h0 + r];
    #pragma unroll
    for (int mi = 0; mi < 2; mi++) {
        const int p = p0 + (mi << 4) + g;
        float* r0 = g_h + ((size_t)(bx << 8) + p) * CMID;
        float* r1 = r0 + 8 * CMID;
        #pragma unroll
        for (int ni = 0; ni < 4; ni++) {
            const int c = (wn << 5) + (ni << 3) + (t4 << 1);
            const float bc0 = b1[c], bc1 = b1[c + 1];
            float2 v0, v1;
            v0.x = fmaxf(fmaf(d[mi][ni][0] + bc0, gs, bb), 0.f);
            v0.y = fmaxf(fmaf(d[mi][ni][1] + bc1, gs, bb), 0.f);
            v1.x = fmaxf(fmaf(d[mi][ni][2] + bc0, gs, bb), 0.f);
            v1.y = fmaxf(fmaf(d[mi][ni][3] + bc1, gs, bb), 0.f);
            *(float2*)(r0 + c) = v0;
            *(float2*)(r1 + c) = v1;
        }
    }
}

// ===========================================================================
// Kernel 2: conv2 via mma.sync tf32 + BN + ReLU + xFB -> g_dyn  (R14, passing)
// ===========================================================================
#define C2_SSTR  72
#define C2_SLAB  (396 * C2_SSTR)
#define C2_WSTR  584
#define C2_WS    (48 * C2_WSTR)
#define C2_SMEM  ((C2_SLAB + C2_WS + 64) * 4)

__global__ __launch_bounds__(512, 1)
void conv2_kernel(const float* __restrict__ b2, const float* __restrict__ gamma2,
                  const float* __restrict__ beta2, const float* __restrict__ bases) {
    extern __shared__ float sm[];
    float* slab = sm;
    float* ws   = sm + C2_SLAB;
    float* bss  = sm + C2_SLAB + C2_WS;

    const int t  = threadIdx.x;
    const int bx = blockIdx.x;
    const int nb = bx >> 4;
    const int h0 = (bx & 15) << 2;

    for (int i = t; i < 6912; i += 512) {
        int row = i / 144, seg = i % 144;
        cp_async16(ws + row * C2_WSTR + seg * 4, g_W2t + row * 576 + seg * 4);
    }
    cp_commit();
    if (t < 54) bss[t] = bases[t];

    const float4* h4 = (const float4*)g_h;
    for (int idx = t; idx < 6 * 66 * 16; idx += 512) {
        int seg = idx & 15;
        int pos = idx >> 4;
        int r   = pos / 66, col = pos % 66;
        int hh  = h0 + r - 1, ww = col - 1;
        float4 v = make_float4(0.f, 0.f, 0.f, 0.f);
        if (hh >= 0 && hh < HH && ww >= 0 && ww < WW)
            v = h4[(size_t)((((nb << 6) + hh) << 6) + ww) * 16 + seg];
        *(float4*)(slab + (r * 66 + col) * C2_SSTR + seg * 4) = v;
    }
    cp_wait<0>();
    __syncthreads();

    const int wid  = t >> 5;
    const int lane = t & 31;
    const int g    = lane >> 2;
    const int t4   = lane & 3;
    const int wm   = wid >> 1;
    const int wn   = wid & 1;
    const int p0   = wm << 5;
    const int r    = p0 >> 6;
    const int wcol = p0 & 63;

    float d[2][3][4] = {};

    #pragma unroll
    for (int kk = 0; kk < 9; kk++) {
        const int kh = kk / 3, kw = kk % 3;
        const float* arow = slab + ((r + kh) * 66 + kw + wcol + g) * C2_SSTR + (t4 << 1);
        const float* brow = ws + (wn * 24 + g) * C2_WSTR + kk * 64 + (t4 << 1);
        #pragma unroll
        for (int kt = 0; kt < 8; kt++) {
            const int k0 = kt << 3;
            uint32_t a[2][4], b[3][2];
            #pragma unroll
            for (int mi = 0; mi < 2; mi++) {
                const float* ap = arow + (mi << 4) * C2_SSTR + k0;
                float2 lo = *(const float2*)ap;
                float2 hi = *(const float2*)(ap + 8 * C2_SSTR);
                a[mi][0] = __float_as_uint(lo.x);
                a[mi][1] = __float_as_uint(hi.x);
                a[mi][2] = __float_as_uint(lo.y);
                a[mi][3] = __float_as_uint(hi.y);
            }
            #pragma unroll
            for (int ni = 0; ni < 3; ni++) {
                float2 bv = *(const float2*)(brow + (ni << 3) * C2_WSTR + k0);
                b[ni][0] = __float_as_uint(bv.x);
                b[ni][1] = __float_as_uint(bv.y);
            }
            #pragma unroll
            for (int mi = 0; mi < 2; mi++)
                #pragma unroll
                for (int ni = 0; ni < 3; ni++)
                    mma_tf32(d[mi][ni], a[mi], b[ni]);
        }
    }
    __syncthreads();

    float* bfs = ws;
    const float invs = rsqrtf(1.0f + 1e-3f);
    const float gs = gamma2[h0 + r] * invs;
    const float bb = beta2[h0 + r];
    #pragma unroll
    for (int mi = 0; mi < 2; mi++) {
        const int p = p0 + (mi << 4) + g;
        #pragma unroll
        for (int ni = 0; ni < 3; ni++) {
            const int c = wn * 24 + (ni << 3) + (t4 << 1);
            if (c < BSZ) {
                const float bj0 = b2[c], bj1 = b2[c + 1];
                bfs[p * 37 + c]           = fmaxf(fmaf(d[mi][ni][0] + bj0, gs, bb), 0.f);
                bfs[p * 37 + c + 1]       = fmaxf(fmaf(d[mi][ni][1] + bj1, gs, bb), 0.f);
                bfs[(p + 8) * 37 + c]     = fmaxf(fmaf(d[mi][ni][2] + bj0, gs, bb), 0.f);
                bfs[(p + 8) * 37 + c + 1] = fmaxf(fmaf(d[mi][ni][3] + bj1, gs, bb), 0.f);
            }
        }
    }
    __syncthreads();

    const int pp = t >> 1;
    const int half = t & 1;
    const float* bf = bfs + pp * 37;
    const int rr = pp >> 6, pw = pp & 63;
    float* outp = g_dyn + (size_t)((((nb << 6) + h0 + rr) << 6) + pw) * 54;
    #pragma unroll
    for (int q = 0; q < 27; q++) {
        int idx = half * 27 + q;
        int m = idx / 9, l = idx % 9;
        float s = 0.f;
        #pragma unroll
        for (int k = 0; k < 6; k++) s = fmaf(bf[m * 6 + k], bss[k * 9 + l], s);
        outp[idx] = s;
    }
}

// ===========================================================================
// Kernel 3a: bases_out A -> g_A[65536][768] (tf32, natural order)  (passing)
// ===========================================================================
#define K3A_SSTR 199
#define K3A_SMEM (CIN * K3A_SSTR * 4)

__global__ __launch_bounds__(256, 2)
void k3a_kernel(const float* __restrict__ x) {
    extern __shared__ float sm[];
    float* slab = sm;

    const int t  = threadIdx.x;
    const int bx = blockIdx.x;
    const int nb = bx >> 6;
    const int h  = bx & 63;

    const float4* x4 = (const float4*)x;
    for (int idx = t; idx < 3 * 66 * 32; idx += 256) {
        int ci4 = idx & 31;
        int col = (idx >> 5) % 66;
        int r   = idx / (32 * 66);
        int hh  = h + r - 1, ww = col - 1;
        float4 v = make_float4(0.f, 0.f, 0.f, 0.f);
        if (hh >= 0 && hh < HH && ww >= 0 && ww < WW)
            v = x4[((((nb << 6) + hh) << 6) + ww) * 32 + ci4];
        int so = r * 66 + col;
        slab[(ci4 * 4 + 0) * K3A_SSTR + so] = v.x;
        slab[(ci4 * 4 + 1) * K3A_SSTR + so] = v.y;
        slab[(ci4 * 4 + 2) * K3A_SSTR + so] = v.z;
        slab[(ci4 * 4 + 3) * K3A_SSTR + so] = v.w;
    }
    __syncthreads();

    const int w    = t >> 5;
    const int lane = t & 31;

    for (int pp = 0; pp < 8; pp++) {
        const int p = (w << 3) + pp;
        const size_t pix = (size_t)(bx << 6) + p;
        const float* dp = g_dyn + pix * 54;
        float dv[54];
        #pragma unroll
        for (int i = 0; i < 54; i++) dv[i] = __ldg(dp + i);

        float* arow = g_A + pix * 768;
        #pragma unroll
        for (int j = 0; j < 4; j++) {
            const int ch = lane + (j << 5);
            float pt[9];
            #pragma unroll
            for (int l = 0; l < 9; l++) {
                const int f  = ch * 9 + l;
                const int cc = f & 127;
                const int pi = f >> 7;
                pt[l] = slab[cc * K3A_SSTR + (pi / 3) * 66 + (pi % 3) + p];
            }
            uint32_t ov[6];
            #pragma unroll
            for (int m = 0; m < 6; m++) {
                float s = 0.f;
                #pragma unroll
                for (int l = 0; l < 9; l++) s = fmaf(dv[m * 9 + l], pt[l], s);
                ov[m] = tf32_rna(s);
            }
            float2* dst = (float2*)(arow + ch * 6);
            dst[0] = make_float2(__uint_as_float(ov[0]), __uint_as_float(ov[1]));
            dst[1] = make_float2(__uint_as_float(ov[2]), __uint_as_float(ov[3]));
            dst[2] = make_float2(__uint_as_float(ov[4]), __uint_as_float(ov[5]));
        }
    }
}

// ===========================================================================
// Kernel 3b: mma.sync tf32 GEMM out[65536,256] = A x B^T + bias
// grid = 512 (mt), block 512 (16 warps, 4m x 4n); block tile 128x256.
// R16: 3-stage cp.async pipeline (prefetch distance 2, cp_wait<1> steady).
// ===========================================================================
#define K3B_STR  40
#define K3B_ACH  (128 * K3B_STR)
#define K3B_BCH  (256 * K3B_STR)
#define K3B_SMEM (3 * (K3B_ACH + K3B_BCH) * 4)   // 184320 B

__global__ __launch_bounds__(512, 1)
void k3b_kernel(const float* __restrict__ bias, float* __restrict__ out) {
    extern __shared__ float sm[];
    float* As[3] = { sm, sm + K3B_ACH, sm + 2 * K3B_ACH };
    float* Bs[3] = { sm + 3 * K3B_ACH,
                     sm + 3 * K3B_ACH + K3B_BCH,
                     sm + 3 * K3B_ACH + 2 * K3B_BCH };

    const int t    = threadIdx.x;
    const int mt   = blockIdx.x;
    const int wid  = t >> 5;
    const int lane = t & 31;
    const int g    = lane >> 2;
    const int tid4 = lane & 3;

    const float* Abase = g_A + (size_t)(mt << 7) * 768;

    // prefetch chunks 0 and 1 as separate commit groups
    #pragma unroll
    for (int pc = 0; pc < 2; pc++) {
        const float* as = Abase + pc * 32;
        const float* bs = g_Bt + pc * 32;
        for (int i = t; i < 1024; i += 512) {
            int row = i >> 3, seg = i & 7;
            cp_async16(As[pc] + row * K3B_STR + seg * 4, as + row * 768 + seg * 4);
        }
        for (int i = t; i < 2048; i += 512) {
            int row = i >> 3, seg = i & 7;
            cp_async16(Bs[pc] + row * K3B_STR + seg * 4, bs + row * 768 + seg * 4);
        }
        cp_commit();
    }

    const int wm = wid >> 2, wn = wid & 3;
    const int m0 = wm << 5, n0 = wn << 6;
    float d[2][8][4] = {};

    for (int kc = 0; kc < 24; kc++) {
        if (kc < 23) cp_wait<1>(); else cp_wait<0>();
        __syncthreads();

        if (kc + 2 < 24) {
            const int nc = kc + 2, buf = nc % 3;
            const float* as = Abase + nc * 32;
            const float* bs = g_Bt + nc * 32;
            for (int i = t; i < 1024; i += 512) {
                int row = i >> 3, seg = i & 7;
                cp_async16(As[buf] + row * K3B_STR + seg * 4, as + row * 768 + seg * 4);
            }
            for (int i = t; i < 2048; i += 512) {
                int row = i >> 3, seg = i & 7;
                cp_async16(Bs[buf] + row * K3B_STR + seg * 4, bs + row * 768 + seg * 4);
            }
            cp_commit();
        }

        const float* Ac = As[kc % 3];
        const float* Bc = Bs[kc % 3];

        #pragma unroll
        for (int kt = 0; kt < 4; kt++) {
            const int k0 = kt << 3;
            uint32_t a[2][4], b[8][2];
            #pragma unroll
            for (int mi = 0; mi < 2; mi++) {
                const float* ap = Ac + (m0 + (mi << 4) + g) * K3B_STR + k0 + (tid4 << 1);
                float2 lo = *(const float2*)ap;
                float2 hi = *(const float2*)(ap + 8 * K3B_STR);
                a[mi][0] = __float_as_uint(lo.x);
                a[mi][1] = __float_as_uint(hi.x);
                a[mi][2] = __float_as_uint(lo.y);
                a[mi][3] = __float_as_uint(hi.y);
            }
            #pragma unroll
            for (int ni = 0; ni < 8; ni++) {
                float2 bv = *(const float2*)(Bc + (n0 + (ni << 3) + g) * K3B_STR
                                             + k0 + (tid4 << 1));
                b[ni][0] = __float_as_uint(bv.x);
                b[ni][1] = __float_as_uint(bv.y);
            }
            #pragma unroll
            for (int mi = 0; mi < 2; mi++)
                #pragma unroll
                for (int ni = 0; ni < 8; ni++)
                    mma_tf32(d[mi][ni], a[mi], b[ni]);
        }
    }

    const size_t rbase = (size_t)(mt << 7) + m0;
    const int    cbase = n0 + (tid4 << 1);
    #pragma unroll
    for (int mi = 0; mi < 2; mi++) {
        float* r0 = out + (rbase + (mi << 4) + g) * OO;
        float* r1 = r0 + 8 * OO;
        #pragma unroll
        for (int ni = 0; ni < 8; ni++) {
            const int c = cbase + (ni << 3);
            const float b0 = bias[c], b1 = bias[c + 1];
            *(float2*)(r0 + c) = make_float2(d[mi][ni][0] + b0, d[mi][ni][1] + b1);
            *(float2*)(r1 + c) = make_float2(d[mi][ni][2] + b0, d[mi][ni][3] + b1);
        }
    }
}

// ===========================================================================
extern "C" void kernel_launch(void* const* d_in, const int* in_sizes, int n_in,
                              void* d_out, int out_size) {
    const float* x      = (const float*)d_in[0];
    const float* w1     = (const float*)d_in[1];
    const float* b1     = (const float*)d_in[2];
    const float* gamma1 = (const float*)d_in[3];
    const float* beta1  = (const float*)d_in[4];
    const float* w2     = (const float*)d_in[5];
    const float* b2     = (const float*)d_in[6];
    const float* gamma2 = (const float*)d_in[7];
    const float* beta2  = (const float*)d_in[8];
    const float* bases  = (const float*)d_in[9];
    const float* coef   = (const float*)d_in[10];
    const float* bias   = (const float*)d_in[11];
    float* out = (float*)d_out;

    cudaFuncSetAttribute(conv1_kernel, cudaFuncAttributeMaxDynamicSharedMemorySize, C1_SMEM);
    cudaFuncSetAttribute(conv2_kernel, cudaFuncAttributeMaxDynamicSharedMemorySize, C2_SMEM);
    cudaFuncSetAttribute(k3a_kernel,   cudaFuncAttributeMaxDynamicSharedMemorySize, K3A_SMEM);
    cudaFuncSetAttribute(k3b_kernel,   cudaFuncAttributeMaxDynamicSharedMemorySize, K3B_SMEM);

    prepW_kernel <<<576, 128>>>(w1);
    prepW2_kernel<<<48,  576>>>(w2);
    prepB_kernel <<<OO,  256>>>(coef);
    conv1_kernel<<<NB * HH / 4, 512, C1_SMEM>>>(x, b1, gamma1, beta1);
    conv2_kernel<<<NB * HH / 4, 512, C2_SMEM>>>(b2, gamma2, beta2, bases);
    k3a_kernel  <<<NB * HH,     256, K3A_SMEM>>>(x);
    k3b_kernel  <<<512,         512, K3B_SMEM>>>(bias, out);
}

// round 17
// speedup vs baseline: 1.1311x; 1.0042x over previous
#include <cuda_runtime.h>
#include <cuda_bf16.h>
#include <cstdint>

// ---------------------------------------------------------------------------
// Conv_DCFD on sm_100 (no tcgen05 in this toolchain): conv1, conv2 and the
// final 1x1 GEMM all run on the tensor pipe via mma.sync tf32 (rna-rounded).
// R17: conv1 weight pipeline -> 3 buffers, prefetch distance 2, cp_wait<1>
// (barriers no longer wait on in-flight loads). Preps merged into one kernel.
// Shapes: N=16,H=64,W=64,C=128, inter=64, bases=36, M=6, O=256
// ---------------------------------------------------------------------------

#define NB   16
#define HH   64
#define WW   64
#define CIN  128
#define CMID 64
#define BSZ  36
#define OO   256

// scratch (no cudaMalloc allowed)
__device__ float g_h   [NB * HH * WW * CMID];     // 16.8 MB
__device__ float g_dyn [NB * HH * WW * 54];       // 14.2 MB
__device__ float g_A   [NB * HH * WW * 768];      // 201 MB (tf32, natural order)
__device__ float g_Bt  [OO * 768];                // 768 KB (B^T, tf32, natural)
__device__ float g_W1t [9 * CMID * CIN];          // w1^T per tap (natural)
__device__ float g_W2t [48 * 576];                // w2^T co-major (natural)

__device__ __forceinline__ void cp_async16(void* smem_dst, const void* gmem_src) {
    unsigned s = (unsigned)__cvta_generic_to_shared(smem_dst);
    asm volatile("cp.async.cg.shared.global [%0], [%1], 16;\n" :: "r"(s), "l"(gmem_src));
}
__device__ __forceinline__ void cp_commit() { asm volatile("cp.async.commit_group;\n"); }
template<int N> __device__ __forceinline__ void cp_wait() {
    asm volatile("cp.async.wait_group %0;\n" :: "n"(N));
}
__device__ __forceinline__ uint32_t tf32_rna(float v) {
    uint32_t r;
    asm("cvt.rna.tf32.f32 %0, %1;" : "=r"(r) : "f"(v));
    return r;
}
__device__ __forceinline__ void mma_tf32(float* d, const uint32_t* a, const uint32_t* b) {
    asm volatile(
        "mma.sync.aligned.m16n8k8.row.col.f32.tf32.tf32.f32 "
        "{%0,%1,%2,%3}, {%4,%5,%6,%7}, {%8,%9}, {%0,%1,%2,%3};"
        : "+f"(d[0]), "+f"(d[1]), "+f"(d[2]), "+f"(d[3])
        : "r"(a[0]), "r"(a[1]), "r"(a[2]), "r"(a[3]), "r"(b[0]), "r"(b[1]));
}

// ===========================================================================
// merged prep kernel: W1 (blocks 0..575), W2 (576..623), B (624..879)
// ===========================================================================
__global__ void prep_kernel(const float* __restrict__ w1, const float* __restrict__ w2,
                            const float* __restrict__ coef) {
    const int b = blockIdx.x;
    const int t = threadIdx.x;
    if (b < 576) {
        // g_W1t[(kk*64+co)*128+ci] = rna(w1[kk][ci][co])
        if (t < 128) {
            const int kk = b >> 6, co = b & 63;
            g_W1t[b * 128 + t] = __uint_as_float(tf32_rna(w1[(kk * 128 + t) * 64 + co]));
        }
    } else if (b < 624) {
        const int n = b - 576;               // 0..47
        for (int k = t; k < 576; k += 256) {
            float v = 0.f;
            if (n < BSZ) {
                const int kk = k >> 6, ci = k & 63;
                v = w2[(kk * 64 + ci) * BSZ + n];
            }
            g_W2t[n * 576 + k] = __uint_as_float(tf32_rna(v));
        }
    } else {
        const int n = b - 624;               // 0..255
        #pragma unroll
        for (int q = 0; q < 3; q++) {
            int k = q * 256 + t;
            g_Bt[n * 768 + k] = __uint_as_float(tf32_rna(coef[k * OO + n]));
        }
    }
}

// ===========================================================================
// Kernel 1: conv1 via mma.sync tf32 + BN(axis=H) + ReLU -> g_h
// R17: grid 256 (4 rows), block 512 (16 warps, 8m x 2n), warp 32px x 32co.
// K=1152 as 18 tap-half steps; weights: 3 buffers, prefetch distance 2,
// cp_wait<1> so barriers never wait on in-flight loads.
// ===========================================================================
#define C1_SSTR  72
#define C1_SLAB  (396 * C1_SSTR)        // 28512 floats
#define C1_WSTR  72
#define C1_WCH   (CMID * C1_WSTR)       // 4608 floats
#define C1_SMEM  ((C1_SLAB + 3 * C1_WCH) * 4)   // 169344 B

__global__ __launch_bounds__(512, 1)
void conv1_kernel(const float* __restrict__ x, const float* __restrict__ b1,
                  const float* __restrict__ gamma1, const float* __restrict__ beta1) {
    extern __shared__ float sm[];
    float* slab = sm;
    float* wbuf = sm + C1_SLAB;

    const int t  = threadIdx.x;
    const int bx = blockIdx.x;
    const int nb = bx >> 4;
    const int h0 = (bx & 15) << 2;

    // weight loader for step s: tap s%9, ci-half s/9 -> buffer s%3
    auto loadw = [&](int s) {
        float* dst = wbuf + (s % 3) * C1_WCH;
        const float* src = g_W1t + (s % 9) * 8192 + (s / 9) * 64;
        for (int i = t; i < 1024; i += 512) {
            int row = i >> 4, seg = i & 15;
            cp_async16(dst + row * C1_WSTR + seg * 4, src + row * 128 + seg * 4);
        }
        cp_commit();
    };

    loadw(0);
    loadw(1);

    // slab fill half 0: rows h0-1..h0+4 (6), cols -1..64 (66), ci 0..63
    const float4* x4 = (const float4*)x;
    for (int idx = t; idx < 6 * 66 * 16; idx += 512) {
        int seg = idx & 15;
        int pos = idx >> 4;
        int rr = pos / 66, col = pos % 66;
        int hh = h0 + rr - 1, ww = col - 1;
        float4 v = make_float4(0.f, 0.f, 0.f, 0.f);
        if (hh >= 0 && hh < HH && ww >= 0 && ww < WW)
            v = x4[((((nb << 6) + hh) << 6) + ww) * 32 + seg];
        float4 o;
        o.x = __uint_as_float(tf32_rna(v.x));
        o.y = __uint_as_float(tf32_rna(v.y));
        o.z = __uint_as_float(tf32_rna(v.z));
        o.w = __uint_as_float(tf32_rna(v.w));
        *(float4*)(slab + (rr * 66 + col) * C1_SSTR + seg * 4) = o;
    }
    cp_wait<1>();       // step 0 weights ready; step 1 still in flight
    __syncthreads();

    const int wid  = t >> 5;
    const int lane = t & 31;
    const int g    = lane >> 2;
    const int t4   = lane & 3;
    const int wm   = wid >> 1;           // 0..7 (32-px group)
    const int wn   = wid & 1;            // 0..1 (32-co group)
    const int p0   = wm << 5;
    const int r    = p0 >> 6;
    const int wcol = p0 & 63;

    float d[2][4][4] = {};

    for (int step = 0; step < 18; step++) {
        // prefetch step+2 into buffer (step+2)%3 (== buffer step-1, all warps
        // are past step-1 thanks to the barrier at the end of step-1)
        if (step < 16) loadw(step + 2);

        const int kk = step % 9;
        const int kh = kk / 3, kw = kk % 3;
        const float* wb = wbuf + (step % 3) * C1_WCH;
        const float* arow = slab + ((r + kh) * 66 + kw + wcol + g) * C1_SSTR + (t4 << 1);

        #pragma unroll
        for (int kt = 0; kt < 8; kt++) {
            const int k0 = kt << 3;
            uint32_t a[2][4], b[4][2];
            #pragma unroll
            for (int mi = 0; mi < 2; mi++) {
                const float* ap = arow + (mi << 4) * C1_SSTR + k0;
                float2 lo = *(const float2*)ap;
                float2 hi = *(const float2*)(ap + 8 * C1_SSTR);
                a[mi][0] = __float_as_uint(lo.x);
                a[mi][1] = __float_as_uint(hi.x);
                a[mi][2] = __float_as_uint(lo.y);
                a[mi][3] = __float_as_uint(hi.y);
            }
            #pragma unroll
            for (int ni = 0; ni < 4; ni++) {
                float2 bv = *(const float2*)(wb + ((wn << 5) + (ni << 3) + g) * C1_WSTR
                                             + k0 + (t4 << 1));
                b[ni][0] = __float_as_uint(bv.x);
                b[ni][1] = __float_as_uint(bv.y);
            }
            #pragma unroll
            for (int mi = 0; mi < 2; mi++)
                #pragma unroll
                for (int ni = 0; ni < 4; ni++)
                    mma_tf32(d[mi][ni], a[mi], b[ni]);
        }

        if (step < 17) {
            if (step == 8) {
                // all compute on ci half 0 done -> reload slab with half 1
                __syncthreads();
                for (int idx = t; idx < 6 * 66 * 16; idx += 512) {
                    int seg = idx & 15;
                    int pos = idx >> 4;
                    int rr = pos / 66, col = pos % 66;
                    int hh = h0 + rr - 1, ww = col - 1;
                    float4 v = make_float4(0.f, 0.f, 0.f, 0.f);
                    if (hh >= 0 && hh < HH && ww >= 0 && ww < WW)
                        v = x4[((((nb << 6) + hh) << 6) + ww) * 32 + 16 + seg];
                    float4 o;
                    o.x = __uint_as_float(tf32_rna(v.x));
                    o.y = __uint_as_float(tf32_rna(v.y));
                    o.z = __uint_as_float(tf32_rna(v.z));
                    o.w = __uint_as_float(tf32_rna(v.w));
                    *(float4*)(slab + (rr * 66 + col) * C1_SSTR + seg * 4) = o;
                }
            }
            cp_wait<1>();       // next step's weights ready; step+2 in flight
            __syncthreads();
        }
    }

    // epilogue: BN(axis=H) + ReLU + bias
    const float invs = rsqrtf(1.0f + 1e-3f);
    const float gs = gamma1[h0 + r] * invs;
    const float bb = beta1[h0 + r];
    #pragma unroll
    for (int mi = 0; mi < 2; mi++) {
        const int p = p0 + (mi << 4) + g;
        float* r0 = g_h + ((size_t)(bx << 8) + p) * CMID;
        float* r1 = r0 + 8 * CMID;
        #pragma unroll
        for (int ni = 0; ni < 4; ni++) {
            const int c = (wn << 5) + (ni << 3) + (t4 << 1);
            const float bc0 = b1[c], bc1 = b1[c + 1];
            float2 v0, v1;
            v0.x = fmaxf(fmaf(d[mi][ni][0] + bc0, gs, bb), 0.f);
            v0.y = fmaxf(fmaf(d[mi][ni][1] + bc1, gs, bb), 0.f);
            v1.x = fmaxf(fmaf(d[mi][ni][2] + bc0, gs, bb), 0.f);
            v1.y = fmaxf(fmaf(d[mi][ni][3] + bc1, gs, bb), 0.f);
            *(float2*)(r0 + c) = v0;
            *(float2*)(r1 + c) = v1;
        }
    }
}

// ===========================================================================
// Kernel 2: conv2 via mma.sync tf32 + BN + ReLU + xFB -> g_dyn  (passing)
// ===========================================================================
#define C2_SSTR  72
#define C2_SLAB  (396 * C2_SSTR)
#define C2_WSTR  584
#define C2_WS    (48 * C2_WSTR)
#define C2_SMEM  ((C2_SLAB + C2_WS + 64) * 4)

__global__ __launch_bounds__(512, 1)
void conv2_kernel(const float* __restrict__ b2, const float* __restrict__ gamma2,
                  const float* __restrict__ beta2, const float* __restrict__ bases) {
    extern __shared__ float sm[];
    float* slab = sm;
    float* ws   = sm + C2_SLAB;
    float* bss  = sm + C2_SLAB + C2_WS;

    const int t  = threadIdx.x;
    const int bx = blockIdx.x;
    const int nb = bx >> 4;
    const int h0 = (bx & 15) << 2;

    for (int i = t; i < 6912; i += 512) {
        int row = i / 144, seg = i % 144;
        cp_async16(ws + row * C2_WSTR + seg * 4, g_W2t + row * 576 + seg * 4);
    }
    cp_commit();
    if (t < 54) bss[t] = bases[t];

    const float4* h4 = (const float4*)g_h;
    for (int idx = t; idx < 6 * 66 * 16; idx += 512) {
        int seg = idx & 15;
        int pos = idx >> 4;
        int r   = pos / 66, col = pos % 66;
        int hh  = h0 + r - 1, ww = col - 1;
        float4 v = make_float4(0.f, 0.f, 0.f, 0.f);
        if (hh >= 0 && hh < HH && ww >= 0 && ww < WW)
            v = h4[(size_t)((((nb << 6) + hh) << 6) + ww) * 16 + seg];
        *(float4*)(slab + (r * 66 + col) * C2_SSTR + seg * 4) = v;
    }
    cp_wait<0>();
    __syncthreads();

    const int wid  = t >> 5;
    const int lane = t & 31;
    const int g    = lane >> 2;
    const int t4   = lane & 3;
    const int wm   = wid >> 1;
    const int wn   = wid & 1;
    const int p0   = wm << 5;
    const int r    = p0 >> 6;
    const int wcol = p0 & 63;

    float d[2][3][4] = {};

    #pragma unroll
    for (int kk = 0; kk < 9; kk++) {
        const int kh = kk / 3, kw = kk % 3;
        const float* arow = slab + ((r + kh) * 66 + kw + wcol + g) * C2_SSTR + (t4 << 1);
        const float* brow = ws + (wn * 24 + g) * C2_WSTR + kk * 64 + (t4 << 1);
        #pragma unroll
        for (int kt = 0; kt < 8; kt++) {
            const int k0 = kt << 3;
            uint32_t a[2][4], b[3][2];
            #pragma unroll
            for (int mi = 0; mi < 2; mi++) {
                const float* ap = arow + (mi << 4) * C2_SSTR + k0;
                float2 lo = *(const float2*)ap;
                float2 hi = *(const float2*)(ap + 8 * C2_SSTR);
                a[mi][0] = __float_as_uint(lo.x);
                a[mi][1] = __float_as_uint(hi.x);
                a[mi][2] = __float_as_uint(lo.y);
                a[mi][3] = __float_as_uint(hi.y);
            }
            #pragma unroll
            for (int ni = 0; ni < 3; ni++) {
                float2 bv = *(const float2*)(brow + (ni << 3) * C2_WSTR + k0);
                b[ni][0] = __float_as_uint(bv.x);
                b[ni][1] = __float_as_uint(bv.y);
            }
            #pragma unroll
            for (int mi = 0; mi < 2; mi++)
                #pragma unroll
                for (int ni = 0; ni < 3; ni++)
                    mma_tf32(d[mi][ni], a[mi], b[ni]);
        }
    }
    __syncthreads();

    float* bfs = ws;
    const float invs = rsqrtf(1.0f + 1e-3f);
    const float gs = gamma2[h0 + r] * invs;
    const float bb = beta2[h0 + r];
    #pragma unroll
    for (int mi = 0; mi < 2; mi++) {
        const int p = p0 + (mi << 4) + g;
        #pragma unroll
        for (int ni = 0; ni < 3; ni++) {
            const int c = wn * 24 + (ni << 3) + (t4 << 1);
            if (c < BSZ) {
                const float bj0 = b2[c], bj1 = b2[c + 1];
                bfs[p * 37 + c]           = fmaxf(fmaf(d[mi][ni][0] + bj0, gs, bb), 0.f);
                bfs[p * 37 + c + 1]       = fmaxf(fmaf(d[mi][ni][1] + bj1, gs, bb), 0.f);
                bfs[(p + 8) * 37 + c]     = fmaxf(fmaf(d[mi][ni][2] + bj0, gs, bb), 0.f);
                bfs[(p + 8) * 37 + c + 1] = fmaxf(fmaf(d[mi][ni][3] + bj1, gs, bb), 0.f);
            }
        }
    }
    __syncthreads();

    const int pp = t >> 1;
    const int half = t & 1;
    const float* bf = bfs + pp * 37;
    const int rr = pp >> 6, pw = pp & 63;
    float* outp = g_dyn + (size_t)((((nb << 6) + h0 + rr) << 6) + pw) * 54;
    #pragma unroll
    for (int q = 0; q < 27; q++) {
        int idx = half * 27 + q;
        int m = idx / 9, l = idx % 9;
        float s = 0.f;
        #pragma unroll
        for (int k = 0; k < 6; k++) s = fmaf(bf[m * 6 + k], bss[k * 9 + l], s);
        outp[idx] = s;
    }
}

// ===========================================================================
// Kernel 3a: bases_out A -> g_A[65536][768] (tf32, natural order)  (passing)
// ===========================================================================
#define K3A_SSTR 199
#define K3A_SMEM (CIN * K3A_SSTR * 4)

__global__ __launch_bounds__(256, 2)
void k3a_kernel(const float* __restrict__ x) {
    extern __shared__ float sm[];
    float* slab = sm;

    const int t  = threadIdx.x;
    const int bx = blockIdx.x;
    const int nb = bx >> 6;
    const int h  = bx & 63;

    const float4* x4 = (const float4*)x;
    for (int idx = t; idx < 3 * 66 * 32; idx += 256) {
        int ci4 = idx & 31;
        int col = (idx >> 5) % 66;
        int r   = idx / (32 * 66);
        int hh  = h + r - 1, ww = col - 1;
        float4 v = make_float4(0.f, 0.f, 0.f, 0.f);
        if (hh >= 0 && hh < HH && ww >= 0 && ww < WW)
            v = x4[((((nb << 6) + hh) << 6) + ww) * 32 + ci4];
        int so = r * 66 + col;
        slab[(ci4 * 4 + 0) * K3A_SSTR + so] = v.x;
        slab[(ci4 * 4 + 1) * K3A_SSTR + so] = v.y;
        slab[(ci4 * 4 + 2) * K3A_SSTR + so] = v.z;
        slab[(ci4 * 4 + 3) * K3A_SSTR + so] = v.w;
    }
    __syncthreads();

    const int w    = t >> 5;
    const int lane = t & 31;

    for (int pp = 0; pp < 8; pp++) {
        const int p = (w << 3) + pp;
        const size_t pix = (size_t)(bx << 6) + p;
        const float* dp = g_dyn + pix * 54;
        float dv[54];
        #pragma unroll
        for (int i = 0; i < 54; i++) dv[i] = __ldg(dp + i);

        float* arow = g_A + pix * 768;
        #pragma unroll
        for (int j = 0; j < 4; j++) {
            const int ch = lane + (j << 5);
            float pt[9];
            #pragma unroll
            for (int l = 0; l < 9; l++) {
                const int f  = ch * 9 + l;
                const int cc = f & 127;
                const int pi = f >> 7;
                pt[l] = slab[cc * K3A_SSTR + (pi / 3) * 66 + (pi % 3) + p];
            }
            uint32_t ov[6];
            #pragma unroll
            for (int m = 0; m < 6; m++) {
                float s = 0.f;
                #pragma unroll
                for (int l = 0; l < 9; l++) s = fmaf(dv[m * 9 + l], pt[l], s);
                ov[m] = tf32_rna(s);
            }
            float2* dst = (float2*)(arow + ch * 6);
            dst[0] = make_float2(__uint_as_float(ov[0]), __uint_as_float(ov[1]));
            dst[1] = make_float2(__uint_as_float(ov[2]), __uint_as_float(ov[3]));
            dst[2] = make_float2(__uint_as_float(ov[4]), __uint_as_float(ov[5]));
        }
    }
}

// ===========================================================================
// Kernel 3b: mma.sync tf32 GEMM out[65536,256] = A x B^T + bias  (passing)
// grid = 512 (mt), block 512 (16 warps, 4m x 4n); block tile 128x256.
// 3-stage cp.async pipeline (prefetch distance 2, cp_wait<1> steady).
// ===========================================================================
#define K3B_STR  40
#define K3B_ACH  (128 * K3B_STR)
#define K3B_BCH  (256 * K3B_STR)
#define K3B_SMEM (3 * (K3B_ACH + K3B_BCH) * 4)   // 184320 B

__global__ __launch_bounds__(512, 1)
void k3b_kernel(const float* __restrict__ bias, float* __restrict__ out) {
    extern __shared__ float sm[];
    float* As[3] = { sm, sm + K3B_ACH, sm + 2 * K3B_ACH };
    float* Bs[3] = { sm + 3 * K3B_ACH,
                     sm + 3 * K3B_ACH + K3B_BCH,
                     sm + 3 * K3B_ACH + 2 * K3B_BCH };

    const int t    = threadIdx.x;
    const int mt   = blockIdx.x;
    const int wid  = t >> 5;
    const int lane = t & 31;
    const int g    = lane >> 2;
    const int tid4 = lane & 3;

    const float* Abase = g_A + (size_t)(mt << 7) * 768;

    #pragma unroll
    for (int pc = 0; pc < 2; pc++) {
        const float* as = Abase + pc * 32;
        const float* bs = g_Bt + pc * 32;
        for (int i = t; i < 1024; i += 512) {
            int row = i >> 3, seg = i & 7;
            cp_async16(As[pc] + row * K3B_STR + seg * 4, as + row * 768 + seg * 4);
        }
        for (int i = t; i < 2048; i += 512) {
            int row = i >> 3, seg = i & 7;
            cp_async16(Bs[pc] + row * K3B_STR + seg * 4, bs + row * 768 + seg * 4);
        }
        cp_commit();
    }

    const int wm = wid >> 2, wn = wid & 3;
    const int m0 = wm << 5, n0 = wn << 6;
    float d[2][8][4] = {};

    for (int kc = 0; kc < 24; kc++) {
        if (kc < 23) cp_wait<1>(); else cp_wait<0>();
        __syncthreads();

        if (kc + 2 < 24) {
            const int nc = kc + 2, buf = nc % 3;
            const float* as = Abase + nc * 32;
            const float* bs = g_Bt + nc * 32;
            for (int i = t; i < 1024; i += 512) {
                int row = i >> 3, seg = i & 7;
                cp_async16(As[buf] + row * K3B_STR + seg * 4, as + row * 768 + seg * 4);
            }
            for (int i = t; i < 2048; i += 512) {
                int row = i >> 3, seg = i & 7;
                cp_async16(Bs[buf] + row * K3B_STR + seg * 4, bs + row * 768 + seg * 4);
            }
            cp_commit();
        }

        const float* Ac = As[kc % 3];
        const float* Bc = Bs[kc % 3];

        #pragma unroll
        for (int kt = 0; kt < 4; kt++) {
            const int k0 = kt << 3;
            uint32_t a[2][4], b[8][2];
            #pragma unroll
            for (int mi = 0; mi < 2; mi++) {
                const float* ap = Ac + (m0 + (mi << 4) + g) * K3B_STR + k0 + (tid4 << 1);
                float2 lo = *(const float2*)ap;
                float2 hi = *(const float2*)(ap + 8 * K3B_STR);
                a[mi][0] = __float_as_uint(lo.x);
                a[mi][1] = __float_as_uint(hi.x);
                a[mi][2] = __float_as_uint(lo.y);
                a[mi][3] = __float_as_uint(hi.y);
            }
            #pragma unroll
            for (int ni = 0; ni < 8; ni++) {
                float2 bv = *(const float2*)(Bc + (n0 + (ni << 3) + g) * K3B_STR
                                             + k0 + (tid4 << 1));
                b[ni][0] = __float_as_uint(bv.x);
                b[ni][1] = __float_as_uint(bv.y);
            }
            #pragma unroll
            for (int mi = 0; mi < 2; mi++)
                #pragma unroll
                for (int ni = 0; ni < 8; ni++)
                    mma_tf32(d[mi][ni], a[mi], b[ni]);
        }
    }

    const size_t rbase = (size_t)(mt << 7) + m0;
    const int    cbase = n0 + (tid4 << 1);
    #pragma unroll
    for (int mi = 0; mi < 2; mi++) {
        float* r0 = out + (rbase + (mi << 4) + g) * OO;
        float* r1 = r0 + 8 * OO;
        #pragma unroll
        for (int ni = 0; ni < 8; ni++) {
            const int c = cbase + (ni << 3);
            const float b0 = bias[c], b1 = bias[c + 1];
            *(float2*)(r0 + c) = make_float2(d[mi][ni][0] + b0, d[mi][ni][1] + b1);
            *(float2*)(r1 + c) = make_float2(d[mi][ni][2] + b0, d[mi][ni][3] + b1);
        }
    }
}

// ===========================================================================
extern "C" void kernel_launch(void* const* d_in, const int* in_sizes, int n_in,
                              void* d_out, int out_size) {
    const float* x      = (const float*)d_in[0];
    const float* w1     = (const float*)d_in[1];
    const float* b1     = (const float*)d_in[2];
    const float* gamma1 = (const float*)d_in[3];
    const float* beta1  = (const float*)d_in[4];
    const float* w2     = (const float*)d_in[5];
    const float* b2     = (const float*)d_in[6];
    const float* gamma2 = (const float*)d_in[7];
    const float* beta2  = (const float*)d_in[8];
    const float* bases  = (const float*)d_in[9];
    const float* coef   = (const float*)d_in[10];
    const float* bias   = (const float*)d_in[11];
    float* out = (float*)d_out;

    cudaFuncSetAttribute(conv1_kernel, cudaFuncAttributeMaxDynamicSharedMemorySize, C1_SMEM);
    cudaFuncSetAttribute(conv2_kernel, cudaFuncAttributeMaxDynamicSharedMemorySize, C2_SMEM);
    cudaFuncSetAttribute(k3a_kernel,   cudaFuncAttributeMaxDynamicSharedMemorySize, K3A_SMEM);
    cudaFuncSetAttribute(k3b_kernel,   cudaFuncAttributeMaxDynamicSharedMemorySize, K3B_SMEM);

    prep_kernel <<<880, 256>>>(w1, w2, coef);
    conv1_kernel<<<NB * HH / 4, 512, C1_SMEM>>>(x, b1, gamma1, beta1);
    conv2_kernel<<<NB * HH / 4, 512, C2_SMEM>>>(b2, gamma2, beta2, bases);
    k3a_kernel  <<<NB * HH,     256, K3A_SMEM>>>(x);
    k3b_kernel  <<<512,         512, K3B_SMEM>>>(bias, out);
}